// round 13
// baseline (speedup 1.0000x reference)
#include <cuda_runtime.h>
#include <cuda_bf16.h>
#include <cstdint>

constexpr int T = 2048, Dm = 1024, H = 16, DH = 64;
constexpr int BHn = 64, M = 8192, KD = 1024, NQKV = 3072;

__device__ __align__(256) int8_t g_xh[(size_t)M * KD],     g_xl[(size_t)M * KD];
__device__ __align__(256) int8_t g_w1h[(size_t)NQKV * KD], g_w1l[(size_t)NQKV * KD]; // W^T [n][k]
__device__ __align__(256) __nv_bfloat16 g_w2h[(size_t)KD * Dm], g_w2l[(size_t)KD * Dm]; // [k][n]
__device__ __align__(256) float g_Qf[(size_t)BHn * T * DH], g_Kf[(size_t)BHn * T * DH];
__device__ __align__(256) __nv_bfloat16 g_Qh[(size_t)BHn * T * DH], g_Ql[(size_t)BHn * T * DH];
__device__ __align__(256) __nv_bfloat16 g_Kh[(size_t)BHn * T * DH], g_Kl[(size_t)BHn * T * DH];
__device__ __align__(256) __nv_bfloat16 g_Vh[(size_t)BHn * T * DH], g_Vl[(size_t)BHn * T * DH];
__device__ __align__(256) __nv_bfloat16 g_AOh[(size_t)M * Dm], g_AOl[(size_t)M * Dm];

__device__ __forceinline__ void cp16(unsigned dst, const void* src) {
    asm volatile("cp.async.cg.shared.global [%0], [%1], 16;\n" :: "r"(dst), "l"(src));
}
#define CP_COMMIT()  asm volatile("cp.async.commit_group;\n" ::: "memory")
#define CP_WAIT_G1() asm volatile("cp.async.wait_group 1;\n" ::: "memory")

__device__ __forceinline__ void ldsm4(unsigned* r, unsigned a) {
    asm volatile("ldmatrix.sync.aligned.m8n8.x4.shared.b16 {%0,%1,%2,%3}, [%4];\n"
                 : "=r"(r[0]), "=r"(r[1]), "=r"(r[2]), "=r"(r[3]) : "r"(a));
}
__device__ __forceinline__ void ldsm4t(unsigned* r, unsigned a) {
    asm volatile("ldmatrix.sync.aligned.m8n8.x4.trans.shared.b16 {%0,%1,%2,%3}, [%4];\n"
                 : "=r"(r[0]), "=r"(r[1]), "=r"(r[2]), "=r"(r[3]) : "r"(a));
}
__device__ __forceinline__ void mma16816(float* c, const unsigned* a, const unsigned* b) {
    asm volatile("mma.sync.aligned.m16n8k16.row.col.f32.bf16.bf16.f32 "
                 "{%0,%1,%2,%3}, {%4,%5,%6,%7}, {%8,%9}, {%0,%1,%2,%3};\n"
                 : "+f"(c[0]), "+f"(c[1]), "+f"(c[2]), "+f"(c[3])
                 : "r"(a[0]), "r"(a[1]), "r"(a[2]), "r"(a[3]), "r"(b[0]), "r"(b[1]));
}
__device__ __forceinline__ void mma_s8(int* c, const unsigned* a, const unsigned* b) {
    asm volatile("mma.sync.aligned.m16n8k32.row.col.s32.s8.s8.s32 "
                 "{%0,%1,%2,%3}, {%4,%5,%6,%7}, {%8,%9}, {%0,%1,%2,%3};\n"
                 : "+r"(c[0]), "+r"(c[1]), "+r"(c[2]), "+r"(c[3])
                 : "r"(a[0]), "r"(a[1]), "r"(a[2]), "r"(a[3]), "r"(b[0]), "r"(b[1]));
}
__device__ __forceinline__ unsigned pack2f(float a, float b) {
    __nv_bfloat162 t = __floats2bfloat162_rn(a, b);
    return *reinterpret_cast<unsigned*>(&t);
}
__device__ __forceinline__ void q15(float v, float S, int8_t& hi, int8_t& lo) {
    int a = __float2int_rn(v * S);
    a = max(-16256, min(16256, a));
    int ah = (a + 64) >> 7;
    hi = (int8_t)ah;
    lo = (int8_t)(a - (ah << 7));
}

// ---- quant / split kernels -------------------------------------------------
__global__ void quantX_kernel(const float4* __restrict__ src, int n4) {
    int i = blockIdx.x * blockDim.x + threadIdx.x;
    if (i >= n4) return;
    float4 v = src[i];
    int8_t h0, h1, h2, h3, l0, l1, l2, l3;
    q15(v.x, 2048.f, h0, l0); q15(v.y, 2048.f, h1, l1);
    q15(v.z, 2048.f, h2, l2); q15(v.w, 2048.f, h3, l3);
    reinterpret_cast<char4*>(g_xh)[i] = make_char4(h0, h1, h2, h3);
    reinterpret_cast<char4*>(g_xl)[i] = make_char4(l0, l1, l2, l3);
}
__global__ void quantWT_kernel(const float* __restrict__ src) {   // Wqkv -> W^T int8 limbs
    __shared__ float tile[32][33];
    const int n0 = blockIdx.x * 32, k0 = blockIdx.y * 32;
    const int tx = threadIdx.x, ty = threadIdx.y;   // 32 x 8
#pragma unroll
    for (int i = 0; i < 32; i += 8)
        tile[ty + i][tx] = src[(size_t)(k0 + ty + i) * NQKV + n0 + tx];
    __syncthreads();
#pragma unroll
    for (int i = 0; i < 32; i += 8) {
        int8_t h, l;
        q15(tile[tx][ty + i], 65536.f, h, l);
        const size_t o = (size_t)(n0 + ty + i) * KD + k0 + tx;
        g_w1h[o] = h; g_w1l[o] = l;
    }
}
__global__ void splitW2_kernel(const float4* __restrict__ src, int n4) {   // Wproj [k][n] bf16 limbs
    __nv_bfloat162* dh = reinterpret_cast<__nv_bfloat162*>(g_w2h);
    __nv_bfloat162* dl = reinterpret_cast<__nv_bfloat162*>(g_w2l);
    int i = blockIdx.x * blockDim.x + threadIdx.x;
    if (i >= n4) return;
    float4 v = src[i];
    __nv_bfloat16 h0 = __float2bfloat16_rn(v.x), h1 = __float2bfloat16_rn(v.y);
    __nv_bfloat16 h2 = __float2bfloat16_rn(v.z), h3 = __float2bfloat16_rn(v.w);
    dh[2 * i]     = __halves2bfloat162(h0, h1);
    dh[2 * i + 1] = __halves2bfloat162(h2, h3);
    dl[2 * i]     = __floats2bfloat162_rn(v.x - __bfloat162float(h0), v.y - __bfloat162float(h1));
    dl[2 * i + 1] = __floats2bfloat162_rn(v.z - __bfloat162float(h2), v.w - __bfloat162float(h3));
}

// ---- QKV GEMM on int8 IMMA (exact 2-limb). 128x128 tile, 256 thr ----------
constexpr int IPITCH = 80;                 // bytes/row, conflict-free
constexpr int IARR = 128 * IPITCH;         // 10240
constexpr int ISTG = 4 * IARR;             // Ah,Al,Bh,Bl
constexpr int ISMEM = 3 * ISTG;            // 122880

__global__ __launch_bounds__(256, 1)
void gemm_i8(const float* __restrict__ bias)
{
    extern __shared__ char ism[];
    const int tid = threadIdx.x, wid = tid >> 5, lane = tid & 31;
    const int m0 = blockIdx.y * 128, n0 = blockIdx.x * 128;
    const int wm = wid >> 2, wn = wid & 3;
    const int g = lane >> 2, q = lane & 3;
    const int seg = lane >> 3, l7 = lane & 7;
    const unsigned sb = (unsigned)__cvta_generic_to_shared(ism);

    auto loadStage = [&](int stage, int k0) {
        const unsigned st = sb + stage * ISTG;
        const int8_t* srcs[4] = { g_xh + (size_t)m0 * KD + k0, g_xl + (size_t)m0 * KD + k0,
                                  g_w1h + (size_t)n0 * KD + k0, g_w1l + (size_t)n0 * KD + k0 };
#pragma unroll
        for (int i = 0; i < 8; i++) {
            int cid = tid + 256 * i;            // 2048 chunks of 16B
            int arr = cid >> 9, idx = cid & 511;
            int r = idx >> 2, c = idx & 3;
            cp16(st + arr * IARR + r * IPITCH + c * 16, srcs[arr] + (size_t)r * KD + c * 16);
        }
    };

    int hh[4][4][4], mid[4][4][4], ll[4][4][4];
#pragma unroll
    for (int a = 0; a < 4; a++)
#pragma unroll
        for (int b = 0; b < 4; b++)
#pragma unroll
            for (int c = 0; c < 4; c++) { hh[a][b][c] = 0; mid[a][b][c] = 0; ll[a][b][c] = 0; }

    constexpr int NIT = KD / 64;               // 16 (64 bytes K per stage)
    loadStage(0, 0);  CP_COMMIT();
    loadStage(1, 64); CP_COMMIT();

    for (int it = 0; it < NIT; ++it) {
        CP_WAIT_G1();
        __syncthreads();
        if (it + 2 < NIT) loadStage((it + 2) % 3, (it + 2) * 64);
        CP_COMMIT();

        const unsigned st = sb + (it % 3) * ISTG;
        const unsigned pAh = st, pAl = st + IARR, pBh = st + 2 * IARR, pBl = st + 3 * IARR;
#pragma unroll
        for (int ks = 0; ks < 2; ks++) {
            const int kb = ks * 32;            // byte offset (32 k-values)
            unsigned bh[2][4], bl[2][4];
#pragma unroll
            for (int np = 0; np < 2; np++) {   // B as n-rows, K-major: non-trans ldsm
                const int nr = wn * 32 + np * 16 + l7 + ((seg >> 1) & 1) * 8;
                const int nc = kb + (seg & 1) * 16;
                ldsm4(bh[np], pBh + nr * IPITCH + nc);
                ldsm4(bl[np], pBl + nr * IPITCH + nc);
            }
#pragma unroll
            for (int mt = 0; mt < 4; mt++) {
                const int r2 = wm * 64 + mt * 16 + l7 + (seg & 1) * 8;
                const int c2 = kb + ((seg >> 1) & 1) * 16;
                unsigned ah[4], al[4];
                ldsm4(ah, pAh + r2 * IPITCH + c2);
                ldsm4(al, pAl + r2 * IPITCH + c2);
#pragma unroll
                for (int nt = 0; nt < 4; nt++) {
                    const unsigned* b2h = &bh[nt >> 1][(nt & 1) * 2];
                    const unsigned* b2l = &bl[nt >> 1][(nt & 1) * 2];
                    mma_s8(hh[mt][nt],  ah, b2h);
                    mma_s8(mid[mt][nt], ah, b2l);
                    mma_s8(mid[mt][nt], al, b2h);
                    mma_s8(ll[mt][nt],  al, b2l);
                }
            }
        }
    }

    const float INV = 1.f / 134217728.f;       // 1/(2^11 * 2^16)
#pragma unroll
    for (int mt = 0; mt < 4; mt++)
#pragma unroll
        for (int i = 0; i < 2; i++) {
            const int row = m0 + wm * 64 + mt * 16 + g + i * 8;
#pragma unroll
            for (int nt = 0; nt < 4; nt++)
#pragma unroll
                for (int j = 0; j < 2; j++) {
                    const int col = n0 + wn * 32 + nt * 8 + 2 * q + j;
                    const int ci = i * 2 + j;
                    const float v = ((float)hh[mt][nt][ci] * 16384.f +
                                     (float)mid[mt][nt][ci] * 128.f +
                                     (float)ll[mt][nt][ci]) * INV + bias[col];
                    const int sel = col >> 10, rem = col & 1023;
                    const int hhd = rem >> 6, dd = rem & 63;
                    const int b = row >> 11, t = row & 2047;
                    const size_t o = (((size_t)(b * H + hhd)) * T + t) * DH + dd;
                    if (sel == 0)      g_Qf[o] = v;
                    else if (sel == 1) g_Kf[o] = v;
                    else {
                        __nv_bfloat16 h = __float2bfloat16_rn(v);
                        g_Vh[o] = h;
                        g_Vl[o] = __float2bfloat16_rn(v - __bfloat162float(h));
                    }
                }
        }
}

// ---- proj GEMM: split-bf16 HMMA (R9 structure, MODE1 only) -----------------
constexpr int APITCH = 40, BPITCH = 136;
constexpr int A_ELE = 128 * APITCH, B_ELE = 32 * BPITCH;
constexpr int GSTAGE = 2 * A_ELE + 2 * B_ELE;
constexpr int GSMEM = 3 * GSTAGE * 2;

__global__ __launch_bounds__(256, 2)
void gemm_proj(const float* __restrict__ bias, float* __restrict__ Cout)
{
    extern __shared__ __nv_bfloat16 gsm[];
    const int tid = threadIdx.x, N = Dm;
    const int m0 = blockIdx.y * 128, n0 = blockIdx.x * 128;
    const int wid = tid >> 5, lane = tid & 31;
    const int wm = wid >> 2, wn = wid & 3;
    const int g = lane >> 2, q = lane & 3;
    const int seg = lane >> 3, l7 = lane & 7;
    const unsigned sbase = (unsigned)__cvta_generic_to_shared(gsm);

    auto loadStage = [&](int stage, int k0) {
        unsigned sb = sbase + stage * GSTAGE * 2;
#pragma unroll
        for (int i = 0; i < 4; i++) {
            int cid = tid + 256 * i, prec = cid >> 9;
            int r = (cid & 511) >> 2, c = cid & 3;
            const __nv_bfloat16* src = (prec ? g_AOl : g_AOh) + (size_t)(m0 + r) * KD + k0 + c * 8;
            cp16(sb + (prec * A_ELE + r * APITCH + c * 8) * 2, src);
        }
#pragma unroll
        for (int i = 0; i < 4; i++) {
            int cid = tid + 256 * i, prec = cid >> 9;
            int rr = (cid & 511) >> 4, cc = cid & 15;
            const __nv_bfloat16* src = (prec ? g_w2l : g_w2h) + (size_t)(k0 + rr) * N + n0 + cc * 8;
            cp16(sb + (2 * A_ELE + prec * B_ELE + rr * BPITCH + cc * 8) * 2, src);
        }
    };

    float acc[4][4][4];
#pragma unroll
    for (int a = 0; a < 4; a++)
#pragma unroll
        for (int b = 0; b < 4; b++)
#pragma unroll
            for (int c = 0; c < 4; c++) acc[a][b][c] = 0.f;

    constexpr int NIT = KD / 32;
    loadStage(0, 0);  CP_COMMIT();
    loadStage(1, 32); CP_COMMIT();
    for (int it = 0; it < NIT; ++it) {
        CP_WAIT_G1();
        __syncthreads();
        if (it + 2 < NIT) loadStage((it + 2) % 3, (it + 2) * 32);
        CP_COMMIT();
        unsigned sb = sbase + (it % 3) * GSTAGE * 2;
        unsigned bB = sb + 2 * A_ELE * 2;
#pragma unroll
        for (int ks = 0; ks < 2; ks++) {
            const int kb = ks * 16;
            unsigned bhf[2][4], blf[2][4];
#pragma unroll
            for (int np = 0; np < 2; np++) {
                int rr = kb + l7 + (seg & 1) * 8;
                int cc = wn * 32 + np * 16 + ((seg >> 1) & 1) * 8;
                unsigned bd = bB + (rr * BPITCH + cc) * 2;
                ldsm4t(bhf[np], bd);
                ldsm4t(blf[np], bd + B_ELE * 2);
            }
#pragma unroll
            for (int mt = 0; mt < 4; mt++) {
                int r2 = wm * 64 + mt * 16 + l7 + (seg & 1) * 8;
                int c2 = kb + ((seg >> 1) & 1) * 8;
                unsigned ad = sb + (r2 * APITCH + c2) * 2;
                unsigned ah[4], al[4];
                ldsm4(ah, ad);
                ldsm4(al, ad + A_ELE * 2);
#pragma unroll
                for (int nt = 0; nt < 4; nt++)
                    mma16816(acc[mt][nt], ah, &bhf[nt >> 1][(nt & 1) * 2]);
#pragma unroll
                for (int nt = 0; nt < 4; nt++)
                    mma16816(acc[mt][nt], ah, &blf[nt >> 1][(nt & 1) * 2]);
#pragma unroll
                for (int nt = 0; nt < 4; nt++)
                    mma16816(acc[mt][nt], al, &bhf[nt >> 1][(nt & 1) * 2]);
            }
        }
    }
#pragma unroll
    for (int mt = 0; mt < 4; mt++)
#pragma unroll
        for (int i = 0; i < 2; i++) {
            const int row = m0 + wm * 64 + mt * 16 + g + i * 8;
#pragma unroll
            for (int nt = 0; nt < 4; nt++)
#pragma unroll
                for (int j = 0; j < 2; j++) {
                    const int col = n0 + wn * 32 + nt * 8 + 2 * q + j;
                    Cout[(size_t)row * N + col] = acc[mt][nt][i * 2 + j] + bias[col];
                }
        }
}

// ---- RoPE ------------------------------------------------------------------
__global__ void rope_split_kernel(const float* __restrict__ cosT,
                                  const float* __restrict__ sinT)
{
    const int idx = blockIdx.x * blockDim.x + threadIdx.x;
    const int d = idx & 31, t = (idx >> 5) & (T - 1);
    const int bh = (idx >> 16) & (BHn - 1), arr = idx >> 22;
    const float* P = arr ? g_Kf : g_Qf;
    __nv_bfloat16* Ph = arr ? g_Kh : g_Qh;
    __nv_bfloat16* Pl = arr ? g_Kl : g_Ql;
    const size_t base = ((size_t)bh * T + t) * DH;
    const float u1 = P[base + d], u2 = P[base + d + 32];
    const float c = cosT[t * DH + d], s = sinT[t * DH + d];
    float o1 = u1 * c - u2 * s, o2 = u2 * c + u1 * s;
    if (arr == 0) { o1 *= 0.125f; o2 *= 0.125f; }
    __nv_bfloat16 h1 = __float2bfloat16_rn(o1), h2 = __float2bfloat16_rn(o2);
    Ph[base + d] = h1;
    Pl[base + d] = __float2bfloat16_rn(o1 - __bfloat162float(h1));
    Ph[base + d + 32] = h2;
    Pl[base + d + 32] = __float2bfloat16_rn(o2 - __bfloat162float(h2));
}

// ---- flash attention (R9, unchanged) ---------------------------------------
constexpr int FPITCH = 72, FTILE = 64 * FPITCH, FSTAGE = 4 * FTILE;
constexpr int FSMEM = 3 * FSTAGE * 2;

__global__ __launch_bounds__(256, 1)
void flash_bf16()
{
    extern __shared__ __nv_bfloat16 fsm[];
    const int tid = threadIdx.x, lane = tid & 31, w = tid >> 5;
    const int g = lane >> 2, q = lane & 3;
    const int seg = lane >> 3, l7 = lane & 7;
    const int bh = blockIdx.y, q0 = blockIdx.x * 128;
    const size_t hb = (size_t)bh * T * DH;
    const unsigned sbase = (unsigned)__cvta_generic_to_shared(fsm);

    unsigned qh[4][4], ql[4][4];
    {
        const unsigned* Qh32 = (const unsigned*)(g_Qh + hb);
        const unsigned* Ql32 = (const unsigned*)(g_Ql + hb);
        const int r0 = q0 + w * 16 + g;
#pragma unroll
        for (int ks = 0; ks < 4; ks++) {
            const int c = ks * 8 + q;
            qh[ks][0] = Qh32[r0 * 32 + c];       qh[ks][1] = Qh32[(r0 + 8) * 32 + c];
            qh[ks][2] = Qh32[r0 * 32 + c + 4];   qh[ks][3] = Qh32[(r0 + 8) * 32 + c + 4];
            ql[ks][0] = Ql32[r0 * 32 + c];       ql[ks][1] = Ql32[(r0 + 8) * 32 + c];
            ql[ks][2] = Ql32[r0 * 32 + c + 4];   ql[ks][3] = Ql32[(r0 + 8) * 32 + c + 4];
        }
    }

    float oacc[8][4];
#pragma unroll
    for (int a = 0; a < 8; a++)
#pragma unroll
        for (int b = 0; b < 4; b++) oacc[a][b] = 0.f;
    float m_i[2] = {-1e30f, -1e30f}, l_i[2] = {0.f, 0.f};

    auto loadKV = [&](int stage, int n0) {
        unsigned sb = sbase + stage * FSTAGE * 2;
        const __nv_bfloat16* srcs[4] = {
            g_Kh + hb + (size_t)n0 * DH, g_Kl + hb + (size_t)n0 * DH,
            g_Vh + hb + (size_t)n0 * DH, g_Vl + hb + (size_t)n0 * DH };
#pragma unroll
        for (int a = 0; a < 4; a++)
#pragma unroll
            for (int i = 0; i < 2; i++) {
                int cid = tid + 256 * i;
                int r = cid >> 3, c = cid & 7;
                cp16(sb + (a * FTILE + r * FPITCH + c * 8) * 2, srcs[a] + r * 64 + c * 8);
            }
    };

    constexpr int NIT = T / 64;
    loadKV(0, 0);  CP_COMMIT();
    loadKV(1, 64); CP_COMMIT();

    for (int it = 0; it < NIT; ++it) {
        CP_WAIT_G1();
        __syncthreads();
        if (it + 2 < NIT) loadKV((it + 2) % 3, (it + 2) * 64);
        CP_COMMIT();

        unsigned sb = sbase + (it % 3) * FSTAGE * 2;
        unsigned kh = sb, kl = sb + FTILE * 2;
        unsigned vh = sb + 2 * FTILE * 2, vl = sb + 3 * FTILE * 2;

        float sacc[8][4];
#pragma unroll
        for (int a = 0; a < 8; a++)
#pragma unroll
            for (int b = 0; b < 4; b++) sacc[a][b] = 0.f;
#pragma unroll
        for (int ks = 0; ks < 4; ks++) {
            const int kb = ks * 16;
#pragma unroll
            for (int npp = 0; npp < 2; npp++) {
                unsigned bkh[2][4], bkl[2][4];
#pragma unroll
                for (int j = 0; j < 2; j++) {
                    const int np = 2 * npp + j;
                    const int nr = np * 16 + l7 + ((seg >> 1) & 1) * 8;
                    const int kc = kb + (seg & 1) * 8;
                    const unsigned off = (nr * FPITCH + kc) * 2;
                    ldsm4(bkh[j], kh + off);
                    ldsm4(bkl[j], kl + off);
                }
                float *a0 = sacc[4 * npp], *a1 = sacc[4 * npp + 1];
                float *a2 = sacc[4 * npp + 2], *a3 = sacc[4 * npp + 3];
                mma16816(a0, qh[ks], bkh[0]); mma16816(a1, qh[ks], bkh[0] + 2);
                mma16816(a2, qh[ks], bkh[1]); mma16816(a3, qh[ks], bkh[1] + 2);
                mma16816(a0, qh[ks], bkl[0]); mma16816(a1, qh[ks], bkl[0] + 2);
                mma16816(a2, qh[ks], bkl[1]); mma16816(a3, qh[ks], bkl[1] + 2);
                mma16816(a0, ql[ks], bkh[0]); mma16816(a1, ql[ks], bkh[0] + 2);
                mma16816(a2, ql[ks], bkh[1]); mma16816(a3, ql[ks], bkh[1] + 2);
            }
        }

#pragma unroll
        for (int r = 0; r < 2; r++) {
            float mx = -1e30f;
#pragma unroll
            for (int nt = 0; nt < 8; nt++)
                mx = fmaxf(mx, fmaxf(sacc[nt][2 * r], sacc[nt][2 * r + 1]));
            mx = fmaxf(mx, __shfl_xor_sync(0xffffffffu, mx, 1));
            mx = fmaxf(mx, __shfl_xor_sync(0xffffffffu, mx, 2));
            const float mnew = fmaxf(m_i[r], mx);
            const float corr = __expf(m_i[r] - mnew);
            m_i[r] = mnew;
            float rs = 0.f;
#pragma unroll
            for (int nt = 0; nt < 8; nt++) {
                sacc[nt][2 * r]     = __expf(sacc[nt][2 * r] - mnew);
                sacc[nt][2 * r + 1] = __expf(sacc[nt][2 * r + 1] - mnew);
                rs += sacc[nt][2 * r] + sacc[nt][2 * r + 1];
            }
            rs += __shfl_xor_sync(0xffffffffu, rs, 1);
            rs += __shfl_xor_sync(0xffffffffu, rs, 2);
            l_i[r] = l_i[r] * corr + rs;
#pragma unroll
            for (int nt = 0; nt < 8; nt++) {
                oacc[nt][2 * r] *= corr;
                oacc[nt][2 * r + 1] *= corr;
            }
        }

        unsigned ph[16], pl[16];
#pragma unroll
        for (int nt = 0; nt < 8; nt++)
#pragma unroll
            for (int hf = 0; hf < 2; hf++) {
                const float p0 = sacc[nt][2 * hf], p1 = sacc[nt][2 * hf + 1];
                const __nv_bfloat16 b0 = __float2bfloat16_rn(p0);
                const __nv_bfloat16 b1 = __float2bfloat16_rn(p1);
                __nv_bfloat162 hi2 = __halves2bfloat162(b0, b1);
                ph[nt * 2 + hf] = *reinterpret_cast<unsigned*>(&hi2);
                pl[nt * 2 + hf] = pack2f(p0 - __bfloat162float(b0), p1 - __bfloat162float(b1));
            }

#pragma unroll
        for (int ks = 0; ks < 4; ks++) {
            const unsigned* aP = &ph[4 * ks];
            const unsigned* aPl = &pl[4 * ks];
#pragma unroll
            for (int npp = 0; npp < 2; npp++) {
                unsigned bvh[2][4], bvl[2][4];
#pragma unroll
                for (int j = 0; j < 2; j++) {
                    const int np = 2 * npp + j;
                    const int vr = ks * 16 + l7 + (seg & 1) * 8;
                    const int vc = np * 16 + ((seg >> 1) & 1) * 8;
                    const unsigned off = (vr * FPITCH + vc) * 2;
                    ldsm4t(bvh[j], vh + off);
                    ldsm4t(bvl[j], vl + off);
                }
                float *a0 = oacc[4 * npp], *a1 = oacc[4 * npp + 1];
                float *a2 = oacc[4 * npp + 2], *a3 = oacc[4 * npp + 3];
                mma16816(a0, aP, bvh[0]);  mma16816(a1, aP, bvh[0] + 2);
                mma16816(a2, aP, bvh[1]);  mma16816(a3, aP, bvh[1] + 2);
                mma16816(a0, aP, bvl[0]);  mma16816(a1, aP, bvl[0] + 2);
                mma16816(a2, aP, bvl[1]);  mma16816(a3, aP, bvl[1] + 2);
                mma16816(a0, aPl, bvh[0]); mma16816(a1, aPl, bvh[0] + 2);
                mma16816(a2, aPl, bvh[1]); mma16816(a3, aPl, bvh[1] + 2);
            }
        }
    }

    const int b = bh >> 4, h = bh & 15;
#pragma unroll
    for (int r = 0; r < 2; r++) {
        const float inv = 1.f / l_i[r];
        const int t = q0 + w * 16 + g + r * 8;
        const size_t base = ((size_t)(b * T + t)) * Dm + h * DH;
#pragma unroll
        for (int nt = 0; nt < 8; nt++) {
            const float v0 = oacc[nt][2 * r] * inv;
            const float v1 = oacc[nt][2 * r + 1] * inv;
            const __nv_bfloat16 h0 = __float2bfloat16_rn(v0);
            const __nv_bfloat16 h1 = __float2bfloat16_rn(v1);
            *reinterpret_cast<__nv_bfloat162*>(g_AOh + base + nt * 8 + 2 * q) =
                __halves2bfloat162(h0, h1);
            *reinterpret_cast<__nv_bfloat162*>(g_AOl + base + nt * 8 + 2 * q) =
                __floats2bfloat162_rn(v0 - __bfloat162float(h0), v1 - __bfloat162float(h1));
        }
    }
}

// ---------------------------------------------------------------------------
extern "C" void kernel_launch(void* const* d_in, const int* in_sizes, int n_in,
                              void* d_out, int out_size)
{
    (void)in_sizes; (void)n_in; (void)out_size;
    const float* x     = (const float*)d_in[0];
    const float* Wqkv  = (const float*)d_in[1];
    const float* bqkv  = (const float*)d_in[2];
    const float* Wproj = (const float*)d_in[3];
    const float* bproj = (const float*)d_in[4];
    const float* cosT  = (const float*)d_in[5];
    const float* sinT  = (const float*)d_in[6];
    float* out = (float*)d_out;

    cudaFuncSetAttribute(gemm_i8,   cudaFuncAttributeMaxDynamicSharedMemorySize, ISMEM);
    cudaFuncSetAttribute(gemm_proj, cudaFuncAttributeMaxDynamicSharedMemorySize, GSMEM);
    cudaFuncSetAttribute(flash_bf16, cudaFuncAttributeMaxDynamicSharedMemorySize, FSMEM);

    quantX_kernel<<<(M * KD / 4) / 256, 256>>>((const float4*)x, M * KD / 4);
    quantWT_kernel<<<dim3(NQKV / 32, KD / 32), dim3(32, 8)>>>(Wqkv);
    splitW2_kernel<<<(KD * Dm / 4) / 256, 256>>>((const float4*)Wproj, KD * Dm / 4);

    gemm_i8<<<dim3(NQKV / 128, M / 128), 256, ISMEM>>>(bqkv);

    rope_split_kernel<<<(2 * BHn * T * 32) / 256, 256>>>(cosT, sinT);

    flash_bf16<<<dim3(T / 128, BHn), 256, FSMEM>>>();

    gemm_proj<<<dim3(Dm / 128, M / 128), 256, GSMEM>>>(bproj, out);
}

// round 14
// speedup vs baseline: 1.1844x; 1.1844x over previous
#include <cuda_runtime.h>
#include <cuda_bf16.h>
#include <cstdint>

constexpr int T = 2048, Dm = 1024, H = 16, DH = 64;
constexpr int BHn = 64, M = 8192, KD = 1024, NQKV = 3072;

__device__ __align__(256) int8_t g_xh[(size_t)M * KD],     g_xl[(size_t)M * KD];
__device__ __align__(256) int8_t g_w1h[(size_t)NQKV * KD], g_w1l[(size_t)NQKV * KD]; // W^T [n][k]
__device__ __align__(256) __nv_bfloat16 g_w2h[(size_t)KD * Dm], g_w2l[(size_t)KD * Dm]; // [k][n]
__device__ __align__(256) float g_Qf[(size_t)BHn * T * DH], g_Kf[(size_t)BHn * T * DH];
__device__ __align__(256) __nv_bfloat16 g_Qh[(size_t)BHn * T * DH], g_Ql[(size_t)BHn * T * DH];
__device__ __align__(256) __nv_bfloat16 g_Kh[(size_t)BHn * T * DH], g_Kl[(size_t)BHn * T * DH];
__device__ __align__(256) __nv_bfloat16 g_Vh[(size_t)BHn * T * DH], g_Vl[(size_t)BHn * T * DH];
__device__ __align__(256) __nv_bfloat16 g_AOh[(size_t)M * Dm], g_AOl[(size_t)M * Dm];

__device__ __forceinline__ void cp16(unsigned dst, const void* src) {
    asm volatile("cp.async.cg.shared.global [%0], [%1], 16;\n" :: "r"(dst), "l"(src));
}
#define CP_COMMIT()  asm volatile("cp.async.commit_group;\n" ::: "memory")
#define CP_WAIT_G1() asm volatile("cp.async.wait_group 1;\n" ::: "memory")

__device__ __forceinline__ void ldsm4(unsigned* r, unsigned a) {
    asm volatile("ldmatrix.sync.aligned.m8n8.x4.shared.b16 {%0,%1,%2,%3}, [%4];\n"
                 : "=r"(r[0]), "=r"(r[1]), "=r"(r[2]), "=r"(r[3]) : "r"(a));
}
__device__ __forceinline__ void ldsm4t(unsigned* r, unsigned a) {
    asm volatile("ldmatrix.sync.aligned.m8n8.x4.trans.shared.b16 {%0,%1,%2,%3}, [%4];\n"
                 : "=r"(r[0]), "=r"(r[1]), "=r"(r[2]), "=r"(r[3]) : "r"(a));
}
__device__ __forceinline__ void mma16816(float* c, const unsigned* a, const unsigned* b) {
    asm volatile("mma.sync.aligned.m16n8k16.row.col.f32.bf16.bf16.f32 "
                 "{%0,%1,%2,%3}, {%4,%5,%6,%7}, {%8,%9}, {%0,%1,%2,%3};\n"
                 : "+f"(c[0]), "+f"(c[1]), "+f"(c[2]), "+f"(c[3])
                 : "r"(a[0]), "r"(a[1]), "r"(a[2]), "r"(a[3]), "r"(b[0]), "r"(b[1]));
}
__device__ __forceinline__ void mma_s8(int* c, const unsigned* a, const unsigned* b) {
    asm volatile("mma.sync.aligned.m16n8k32.row.col.s32.s8.s8.s32 "
                 "{%0,%1,%2,%3}, {%4,%5,%6,%7}, {%8,%9}, {%0,%1,%2,%3};\n"
                 : "+r"(c[0]), "+r"(c[1]), "+r"(c[2]), "+r"(c[3])
                 : "r"(a[0]), "r"(a[1]), "r"(a[2]), "r"(a[3]), "r"(b[0]), "r"(b[1]));
}
__device__ __forceinline__ unsigned pack2f(float a, float b) {
    __nv_bfloat162 t = __floats2bfloat162_rn(a, b);
    return *reinterpret_cast<unsigned*>(&t);
}
__device__ __forceinline__ void q15(float v, float S, int8_t& hi, int8_t& lo) {
    int a = __float2int_rn(v * S);
    a = max(-16256, min(16256, a));
    int ah = (a + 64) >> 7;
    hi = (int8_t)ah;
    lo = (int8_t)(a - (ah << 7));
}

// ---- quant / split kernels -------------------------------------------------
__global__ void quantX_kernel(const float4* __restrict__ src, int n4) {
    int i = blockIdx.x * blockDim.x + threadIdx.x;
    if (i >= n4) return;
    float4 v = src[i];
    int8_t h0, h1, h2, h3, l0, l1, l2, l3;
    q15(v.x, 2048.f, h0, l0); q15(v.y, 2048.f, h1, l1);
    q15(v.z, 2048.f, h2, l2); q15(v.w, 2048.f, h3, l3);
    reinterpret_cast<char4*>(g_xh)[i] = make_char4(h0, h1, h2, h3);
    reinterpret_cast<char4*>(g_xl)[i] = make_char4(l0, l1, l2, l3);
}
__global__ void quantWT_kernel(const float* __restrict__ src) {   // Wqkv -> W^T int8 limbs
    __shared__ float tile[32][33];
    const int n0 = blockIdx.x * 32, k0 = blockIdx.y * 32;
    const int tx = threadIdx.x, ty = threadIdx.y;   // 32 x 8
#pragma unroll
    for (int i = 0; i < 32; i += 8)
        tile[ty + i][tx] = src[(size_t)(k0 + ty + i) * NQKV + n0 + tx];
    __syncthreads();
#pragma unroll
    for (int i = 0; i < 32; i += 8) {
        int8_t h, l;
        q15(tile[tx][ty + i], 65536.f, h, l);
        const size_t o = (size_t)(n0 + ty + i) * KD + k0 + tx;
        g_w1h[o] = h; g_w1l[o] = l;
    }
}
__global__ void splitW2_kernel(const float4* __restrict__ src, int n4) {   // Wproj [k][n] bf16 limbs
    __nv_bfloat162* dh = reinterpret_cast<__nv_bfloat162*>(g_w2h);
    __nv_bfloat162* dl = reinterpret_cast<__nv_bfloat162*>(g_w2l);
    int i = blockIdx.x * blockDim.x + threadIdx.x;
    if (i >= n4) return;
    float4 v = src[i];
    __nv_bfloat16 h0 = __float2bfloat16_rn(v.x), h1 = __float2bfloat16_rn(v.y);
    __nv_bfloat16 h2 = __float2bfloat16_rn(v.z), h3 = __float2bfloat16_rn(v.w);
    dh[2 * i]     = __halves2bfloat162(h0, h1);
    dh[2 * i + 1] = __halves2bfloat162(h2, h3);
    dl[2 * i]     = __floats2bfloat162_rn(v.x - __bfloat162float(h0), v.y - __bfloat162float(h1));
    dl[2 * i + 1] = __floats2bfloat162_rn(v.z - __bfloat162float(h2), v.w - __bfloat162float(h3));
}

// ---- QKV GEMM on int8 IMMA. 2 acc sets (hh, mid); ll term dropped ----------
constexpr int IPITCH = 80;
constexpr int IARR = 128 * IPITCH;
constexpr int ISTG = 4 * IARR;
constexpr int ISMEM = 3 * ISTG;            // 122880

__global__ __launch_bounds__(256, 1)
void gemm_i8(const float* __restrict__ bias)
{
    extern __shared__ char ism[];
    const int tid = threadIdx.x, wid = tid >> 5, lane = tid & 31;
    const int m0 = blockIdx.y * 128, n0 = blockIdx.x * 128;
    const int wm = wid >> 2, wn = wid & 3;
    const int g = lane >> 2, q = lane & 3;
    const int seg = lane >> 3, l7 = lane & 7;
    const unsigned sb = (unsigned)__cvta_generic_to_shared(ism);

    auto loadStage = [&](int stage, int k0) {
        const unsigned st = sb + stage * ISTG;
        const int8_t* srcs[4] = { g_xh + (size_t)m0 * KD + k0, g_xl + (size_t)m0 * KD + k0,
                                  g_w1h + (size_t)n0 * KD + k0, g_w1l + (size_t)n0 * KD + k0 };
#pragma unroll
        for (int i = 0; i < 8; i++) {
            int cid = tid + 256 * i;
            int arr = cid >> 9, idx = cid & 511;
            int r = idx >> 2, c = idx & 3;
            cp16(st + arr * IARR + r * IPITCH + c * 16, srcs[arr] + (size_t)r * KD + c * 16);
        }
    };

    int hh[4][4][4], mid[4][4][4];
#pragma unroll
    for (int a = 0; a < 4; a++)
#pragma unroll
        for (int b = 0; b < 4; b++)
#pragma unroll
            for (int c = 0; c < 4; c++) { hh[a][b][c] = 0; mid[a][b][c] = 0; }

    constexpr int NIT = KD / 64;
    loadStage(0, 0);  CP_COMMIT();
    loadStage(1, 64); CP_COMMIT();

    for (int it = 0; it < NIT; ++it) {
        CP_WAIT_G1();
        __syncthreads();
        if (it + 2 < NIT) loadStage((it + 2) % 3, (it + 2) * 64);
        CP_COMMIT();

        const unsigned st = sb + (it % 3) * ISTG;
        const unsigned pAh = st, pAl = st + IARR, pBh = st + 2 * IARR, pBl = st + 3 * IARR;
#pragma unroll
        for (int ks = 0; ks < 2; ks++) {
            const int kb = ks * 32;
            unsigned bh[2][4], bl[2][4];
#pragma unroll
            for (int np = 0; np < 2; np++) {
                const int nr = wn * 32 + np * 16 + l7 + ((seg >> 1) & 1) * 8;
                const int nc = kb + (seg & 1) * 16;
                ldsm4(bh[np], pBh + nr * IPITCH + nc);
                ldsm4(bl[np], pBl + nr * IPITCH + nc);
            }
#pragma unroll
            for (int mt = 0; mt < 4; mt++) {
                const int r2 = wm * 64 + mt * 16 + l7 + (seg & 1) * 8;
                const int c2 = kb + ((seg >> 1) & 1) * 16;
                unsigned ah[4], al[4];
                ldsm4(ah, pAh + r2 * IPITCH + c2);
                ldsm4(al, pAl + r2 * IPITCH + c2);
#pragma unroll
                for (int nt = 0; nt < 4; nt++) {
                    const unsigned* b2h = &bh[nt >> 1][(nt & 1) * 2];
                    const unsigned* b2l = &bl[nt >> 1][(nt & 1) * 2];
                    mma_s8(hh[mt][nt],  ah, b2h);
                    mma_s8(mid[mt][nt], ah, b2l);
                    mma_s8(mid[mt][nt], al, b2h);
                }
            }
        }
    }

    const float INV = 1.f / 134217728.f;       // 1/(2^11 * 2^16)
#pragma unroll
    for (int mt = 0; mt < 4; mt++)
#pragma unroll
        for (int i = 0; i < 2; i++) {
            const int row = m0 + wm * 64 + mt * 16 + g + i * 8;
#pragma unroll
            for (int nt = 0; nt < 4; nt++)
#pragma unroll
                for (int j = 0; j < 2; j++) {
                    const int col = n0 + wn * 32 + nt * 8 + 2 * q + j;
                    const int ci = i * 2 + j;
                    const float v = ((float)hh[mt][nt][ci] * 16384.f +
                                     (float)mid[mt][nt][ci] * 128.f) * INV + bias[col];
                    const int sel = col >> 10, rem = col & 1023;
                    const int hhd = rem >> 6, dd = rem & 63;
                    const int b = row >> 11, t = row & 2047;
                    const size_t o = (((size_t)(b * H + hhd)) * T + t) * DH + dd;
                    if (sel == 0)      g_Qf[o] = v;
                    else if (sel == 1) g_Kf[o] = v;
                    else {
                        __nv_bfloat16 h = __float2bfloat16_rn(v);
                        g_Vh[o] = h;
                        g_Vl[o] = __float2bfloat16_rn(v - __bfloat162float(h));
                    }
                }
        }
}

// ---- proj GEMM: split-bf16 HMMA --------------------------------------------
constexpr int APITCH = 40, BPITCH = 136;
constexpr int A_ELE = 128 * APITCH, B_ELE = 32 * BPITCH;
constexpr int GSTAGE = 2 * A_ELE + 2 * B_ELE;
constexpr int GSMEM = 3 * GSTAGE * 2;

__global__ __launch_bounds__(256, 2)
void gemm_proj(const float* __restrict__ bias, float* __restrict__ Cout)
{
    extern __shared__ __nv_bfloat16 gsm[];
    const int tid = threadIdx.x, N = Dm;
    const int m0 = blockIdx.y * 128, n0 = blockIdx.x * 128;
    const int wid = tid >> 5, lane = tid & 31;
    const int wm = wid >> 2, wn = wid & 3;
    const int g = lane >> 2, q = lane & 3;
    const int seg = lane >> 3, l7 = lane & 7;
    const unsigned sbase = (unsigned)__cvta_generic_to_shared(gsm);

    auto loadStage = [&](int stage, int k0) {
        unsigned sb = sbase + stage * GSTAGE * 2;
#pragma unroll
        for (int i = 0; i < 4; i++) {
            int cid = tid + 256 * i, prec = cid >> 9;
            int r = (cid & 511) >> 2, c = cid & 3;
            const __nv_bfloat16* src = (prec ? g_AOl : g_AOh) + (size_t)(m0 + r) * KD + k0 + c * 8;
            cp16(sb + (prec * A_ELE + r * APITCH + c * 8) * 2, src);
        }
#pragma unroll
        for (int i = 0; i < 4; i++) {
            int cid = tid + 256 * i, prec = cid >> 9;
            int rr = (cid & 511) >> 4, cc = cid & 15;
            const __nv_bfloat16* src = (prec ? g_w2l : g_w2h) + (size_t)(k0 + rr) * N + n0 + cc * 8;
            cp16(sb + (2 * A_ELE + prec * B_ELE + rr * BPITCH + cc * 8) * 2, src);
        }
    };

    float acc[4][4][4];
#pragma unroll
    for (int a = 0; a < 4; a++)
#pragma unroll
        for (int b = 0; b < 4; b++)
#pragma unroll
            for (int c = 0; c < 4; c++) acc[a][b][c] = 0.f;

    constexpr int NIT = KD / 32;
    loadStage(0, 0);  CP_COMMIT();
    loadStage(1, 32); CP_COMMIT();
    for (int it = 0; it < NIT; ++it) {
        CP_WAIT_G1();
        __syncthreads();
        if (it + 2 < NIT) loadStage((it + 2) % 3, (it + 2) * 32);
        CP_COMMIT();
        unsigned sb = sbase + (it % 3) * GSTAGE * 2;
        unsigned bB = sb + 2 * A_ELE * 2;
#pragma unroll
        for (int ks = 0; ks < 2; ks++) {
            const int kb = ks * 16;
            unsigned bhf[2][4], blf[2][4];
#pragma unroll
            for (int np = 0; np < 2; np++) {
                int rr = kb + l7 + (seg & 1) * 8;
                int cc = wn * 32 + np * 16 + ((seg >> 1) & 1) * 8;
                unsigned bd = bB + (rr * BPITCH + cc) * 2;
                ldsm4t(bhf[np], bd);
                ldsm4t(blf[np], bd + B_ELE * 2);
            }
#pragma unroll
            for (int mt = 0; mt < 4; mt++) {
                int r2 = wm * 64 + mt * 16 + l7 + (seg & 1) * 8;
                int c2 = kb + ((seg >> 1) & 1) * 8;
                unsigned ad = sb + (r2 * APITCH + c2) * 2;
                unsigned ah[4], al[4];
                ldsm4(ah, ad);
                ldsm4(al, ad + A_ELE * 2);
#pragma unroll
                for (int nt = 0; nt < 4; nt++)
                    mma16816(acc[mt][nt], ah, &bhf[nt >> 1][(nt & 1) * 2]);
#pragma unroll
                for (int nt = 0; nt < 4; nt++)
                    mma16816(acc[mt][nt], ah, &blf[nt >> 1][(nt & 1) * 2]);
#pragma unroll
                for (int nt = 0; nt < 4; nt++)
                    mma16816(acc[mt][nt], al, &bhf[nt >> 1][(nt & 1) * 2]);
            }
        }
    }
#pragma unroll
    for (int mt = 0; mt < 4; mt++)
#pragma unroll
        for (int i = 0; i < 2; i++) {
            const int row = m0 + wm * 64 + mt * 16 + g + i * 8;
#pragma unroll
            for (int nt = 0; nt < 4; nt++)
#pragma unroll
                for (int j = 0; j < 2; j++) {
                    const int col = n0 + wn * 32 + nt * 8 + 2 * q + j;
                    Cout[(size_t)row * N + col] = acc[mt][nt][i * 2 + j] + bias[col];
                }
        }
}

// ---- RoPE ------------------------------------------------------------------
__global__ void rope_split_kernel(const float* __restrict__ cosT,
                                  const float* __restrict__ sinT)
{
    const int idx = blockIdx.x * blockDim.x + threadIdx.x;
    const int d = idx & 31, t = (idx >> 5) & (T - 1);
    const int bh = (idx >> 16) & (BHn - 1), arr = idx >> 22;
    const float* P = arr ? g_Kf : g_Qf;
    __nv_bfloat16* Ph = arr ? g_Kh : g_Qh;
    __nv_bfloat16* Pl = arr ? g_Kl : g_Ql;
    const size_t base = ((size_t)bh * T + t) * DH;
    const float u1 = P[base + d], u2 = P[base + d + 32];
    const float c = cosT[t * DH + d], s = sinT[t * DH + d];
    float o1 = u1 * c - u2 * s, o2 = u2 * c + u1 * s;
    if (arr == 0) { o1 *= 0.125f; o2 *= 0.125f; }
    __nv_bfloat16 h1 = __float2bfloat16_rn(o1), h2 = __float2bfloat16_rn(o2);
    Ph[base + d] = h1;
    Pl[base + d] = __float2bfloat16_rn(o1 - __bfloat162float(h1));
    Ph[base + d + 32] = h2;
    Pl[base + d + 32] = __float2bfloat16_rn(o2 - __bfloat162float(h2));
}

// ---- flash attention (unchanged) -------------------------------------------
constexpr int FPITCH = 72, FTILE = 64 * FPITCH, FSTAGE = 4 * FTILE;
constexpr int FSMEM = 3 * FSTAGE * 2;

__global__ __launch_bounds__(256, 1)
void flash_bf16()
{
    extern __shared__ __nv_bfloat16 fsm[];
    const int tid = threadIdx.x, lane = tid & 31, w = tid >> 5;
    const int g = lane >> 2, q = lane & 3;
    const int seg = lane >> 3, l7 = lane & 7;
    const int bh = blockIdx.y, q0 = blockIdx.x * 128;
    const size_t hb = (size_t)bh * T * DH;
    const unsigned sbase = (unsigned)__cvta_generic_to_shared(fsm);

    unsigned qh[4][4], ql[4][4];
    {
        const unsigned* Qh32 = (const unsigned*)(g_Qh + hb);
        const unsigned* Ql32 = (const unsigned*)(g_Ql + hb);
        const int r0 = q0 + w * 16 + g;
#pragma unroll
        for (int ks = 0; ks < 4; ks++) {
            const int c = ks * 8 + q;
            qh[ks][0] = Qh32[r0 * 32 + c];       qh[ks][1] = Qh32[(r0 + 8) * 32 + c];
            qh[ks][2] = Qh32[r0 * 32 + c + 4];   qh[ks][3] = Qh32[(r0 + 8) * 32 + c + 4];
            ql[ks][0] = Ql32[r0 * 32 + c];       ql[ks][1] = Ql32[(r0 + 8) * 32 + c];
            ql[ks][2] = Ql32[r0 * 32 + c + 4];   ql[ks][3] = Ql32[(r0 + 8) * 32 + c + 4];
        }
    }

    float oacc[8][4];
#pragma unroll
    for (int a = 0; a < 8; a++)
#pragma unroll
        for (int b = 0; b < 4; b++) oacc[a][b] = 0.f;
    float m_i[2] = {-1e30f, -1e30f}, l_i[2] = {0.f, 0.f};

    auto loadKV = [&](int stage, int n0) {
        unsigned sb = sbase + stage * FSTAGE * 2;
        const __nv_bfloat16* srcs[4] = {
            g_Kh + hb + (size_t)n0 * DH, g_Kl + hb + (size_t)n0 * DH,
            g_Vh + hb + (size_t)n0 * DH, g_Vl + hb + (size_t)n0 * DH };
#pragma unroll
        for (int a = 0; a < 4; a++)
#pragma unroll
            for (int i = 0; i < 2; i++) {
                int cid = tid + 256 * i;
                int r = cid >> 3, c = cid & 7;
                cp16(sb + (a * FTILE + r * FPITCH + c * 8) * 2, srcs[a] + r * 64 + c * 8);
            }
    };

    constexpr int NIT = T / 64;
    loadKV(0, 0);  CP_COMMIT();
    loadKV(1, 64); CP_COMMIT();

    for (int it = 0; it < NIT; ++it) {
        CP_WAIT_G1();
        __syncthreads();
        if (it + 2 < NIT) loadKV((it + 2) % 3, (it + 2) * 64);
        CP_COMMIT();

        unsigned sb = sbase + (it % 3) * FSTAGE * 2;
        unsigned kh = sb, kl = sb + FTILE * 2;
        unsigned vh = sb + 2 * FTILE * 2, vl = sb + 3 * FTILE * 2;

        float sacc[8][4];
#pragma unroll
        for (int a = 0; a < 8; a++)
#pragma unroll
            for (int b = 0; b < 4; b++) sacc[a][b] = 0.f;
#pragma unroll
        for (int ks = 0; ks < 4; ks++) {
            const int kb = ks * 16;
#pragma unroll
            for (int npp = 0; npp < 2; npp++) {
                unsigned bkh[2][4], bkl[2][4];
#pragma unroll
                for (int j = 0; j < 2; j++) {
                    const int np = 2 * npp + j;
                    const int nr = np * 16 + l7 + ((seg >> 1) & 1) * 8;
                    const int kc = kb + (seg & 1) * 8;
                    const unsigned off = (nr * FPITCH + kc) * 2;
                    ldsm4(bkh[j], kh + off);
                    ldsm4(bkl[j], kl + off);
                }
                float *a0 = sacc[4 * npp], *a1 = sacc[4 * npp + 1];
                float *a2 = sacc[4 * npp + 2], *a3 = sacc[4 * npp + 3];
                mma16816(a0, qh[ks], bkh[0]); mma16816(a1, qh[ks], bkh[0] + 2);
                mma16816(a2, qh[ks], bkh[1]); mma16816(a3, qh[ks], bkh[1] + 2);
                mma16816(a0, qh[ks], bkl[0]); mma16816(a1, qh[ks], bkl[0] + 2);
                mma16816(a2, qh[ks], bkl[1]); mma16816(a3, qh[ks], bkl[1] + 2);
                mma16816(a0, ql[ks], bkh[0]); mma16816(a1, ql[ks], bkh[0] + 2);
                mma16816(a2, ql[ks], bkh[1]); mma16816(a3, ql[ks], bkh[1] + 2);
            }
        }

#pragma unroll
        for (int r = 0; r < 2; r++) {
            float mx = -1e30f;
#pragma unroll
            for (int nt = 0; nt < 8; nt++)
                mx = fmaxf(mx, fmaxf(sacc[nt][2 * r], sacc[nt][2 * r + 1]));
            mx = fmaxf(mx, __shfl_xor_sync(0xffffffffu, mx, 1));
            mx = fmaxf(mx, __shfl_xor_sync(0xffffffffu, mx, 2));
            const float mnew = fmaxf(m_i[r], mx);
            const float corr = __expf(m_i[r] - mnew);
            m_i[r] = mnew;
            float rs = 0.f;
#pragma unroll
            for (int nt = 0; nt < 8; nt++) {
                sacc[nt][2 * r]     = __expf(sacc[nt][2 * r] - mnew);
                sacc[nt][2 * r + 1] = __expf(sacc[nt][2 * r + 1] - mnew);
                rs += sacc[nt][2 * r] + sacc[nt][2 * r + 1];
            }
            rs += __shfl_xor_sync(0xffffffffu, rs, 1);
            rs += __shfl_xor_sync(0xffffffffu, rs, 2);
            l_i[r] = l_i[r] * corr + rs;
#pragma unroll
            for (int nt = 0; nt < 8; nt++) {
                oacc[nt][2 * r] *= corr;
                oacc[nt][2 * r + 1] *= corr;
            }
        }

        unsigned ph[16], pl[16];
#pragma unroll
        for (int nt = 0; nt < 8; nt++)
#pragma unroll
            for (int hf = 0; hf < 2; hf++) {
                const float p0 = sacc[nt][2 * hf], p1 = sacc[nt][2 * hf + 1];
                const __nv_bfloat16 b0 = __float2bfloat16_rn(p0);
                const __nv_bfloat16 b1 = __float2bfloat16_rn(p1);
                __nv_bfloat162 hi2 = __halves2bfloat162(b0, b1);
                ph[nt * 2 + hf] = *reinterpret_cast<unsigned*>(&hi2);
                pl[nt * 2 + hf] = pack2f(p0 - __bfloat162float(b0), p1 - __bfloat162float(b1));
            }

#pragma unroll
        for (int ks = 0; ks < 4; ks++) {
            const unsigned* aP = &ph[4 * ks];
            const unsigned* aPl = &pl[4 * ks];
#pragma unroll
            for (int npp = 0; npp < 2; npp++) {
                unsigned bvh[2][4], bvl[2][4];
#pragma unroll
                for (int j = 0; j < 2; j++) {
                    const int np = 2 * npp + j;
                    const int vr = ks * 16 + l7 + (seg & 1) * 8;
                    const int vc = np * 16 + ((seg >> 1) & 1) * 8;
                    const unsigned off = (vr * FPITCH + vc) * 2;
                    ldsm4t(bvh[j], vh + off);
                    ldsm4t(bvl[j], vl + off);
                }
                float *a0 = oacc[4 * npp], *a1 = oacc[4 * npp + 1];
                float *a2 = oacc[4 * npp + 2], *a3 = oacc[4 * npp + 3];
                mma16816(a0, aP, bvh[0]);  mma16816(a1, aP, bvh[0] + 2);
                mma16816(a2, aP, bvh[1]);  mma16816(a3, aP, bvh[1] + 2);
                mma16816(a0, aP, bvl[0]);  mma16816(a1, aP, bvl[0] + 2);
                mma16816(a2, aP, bvl[1]);  mma16816(a3, aP, bvl[1] + 2);
                mma16816(a0, aPl, bvh[0]); mma16816(a1, aPl, bvh[0] + 2);
                mma16816(a2, aPl, bvh[1]); mma16816(a3, aPl, bvh[1] + 2);
            }
        }
    }

    const int b = bh >> 4, h = bh & 15;
#pragma unroll
    for (int r = 0; r < 2; r++) {
        const float inv = 1.f / l_i[r];
        const int t = q0 + w * 16 + g + r * 8;
        const size_t base = ((size_t)(b * T + t)) * Dm + h * DH;
#pragma unroll
        for (int nt = 0; nt < 8; nt++) {
            const float v0 = oacc[nt][2 * r] * inv;
            const float v1 = oacc[nt][2 * r + 1] * inv;
            const __nv_bfloat16 h0 = __float2bfloat16_rn(v0);
            const __nv_bfloat16 h1 = __float2bfloat16_rn(v1);
            *reinterpret_cast<__nv_bfloat162*>(g_AOh + base + nt * 8 + 2 * q) =
                __halves2bfloat162(h0, h1);
            *reinterpret_cast<__nv_bfloat162*>(g_AOl + base + nt * 8 + 2 * q) =
                __floats2bfloat162_rn(v0 - __bfloat162float(h0), v1 - __bfloat162float(h1));
        }
    }
}

// ---------------------------------------------------------------------------
extern "C" void kernel_launch(void* const* d_in, const int* in_sizes, int n_in,
                              void* d_out, int out_size)
{
    (void)in_sizes; (void)n_in; (void)out_size;
    const float* x     = (const float*)d_in[0];
    const float* Wqkv  = (const float*)d_in[1];
    const float* bqkv  = (const float*)d_in[2];
    const float* Wproj = (const float*)d_in[3];
    const float* bproj = (const float*)d_in[4];
    const float* cosT  = (const float*)d_in[5];
    const float* sinT  = (const float*)d_in[6];
    float* out = (float*)d_out;

    cudaFuncSetAttribute(gemm_i8,   cudaFuncAttributeMaxDynamicSharedMemorySize, ISMEM);
    cudaFuncSetAttribute(gemm_proj, cudaFuncAttributeMaxDynamicSharedMemorySize, GSMEM);
    cudaFuncSetAttribute(flash_bf16, cudaFuncAttributeMaxDynamicSharedMemorySize, FSMEM);

    quantX_kernel<<<(M * KD / 4) / 256, 256>>>((const float4*)x, M * KD / 4);
    quantWT_kernel<<<dim3(NQKV / 32, KD / 32), dim3(32, 8)>>>(Wqkv);
    splitW2_kernel<<<(KD * Dm / 4) / 256, 256>>>((const float4*)Wproj, KD * Dm / 4);

    gemm_i8<<<dim3(NQKV / 128, M / 128), 256, ISMEM>>>(bqkv);

    rope_split_kernel<<<(2 * BHn * T * 32) / 256, 256>>>(cosT, sinT);

    flash_bf16<<<dim3(T / 128, BHn), 256, FSMEM>>>();

    gemm_proj<<<dim3(Dm / 128, M / 128), 256, GSMEM>>>(bproj, out);
}

// round 15
// speedup vs baseline: 1.9658x; 1.6597x over previous
#include <cuda_runtime.h>
#include <cuda_bf16.h>

// ---------------------------------------------------------------------------
// FlashMultiHeadAttention, split-bf16 HMMA everywhere (R9 pipeline).
// R15: flash reshaped for occupancy — 128-thr CTAs, 2-stage K/V pipeline,
// 3 CTAs/SM (12 warps/SM vs 8). Race-safe prefetch ordering.
// ---------------------------------------------------------------------------

constexpr int Bb  = 4;
constexpr int T   = 2048;
constexpr int Dm  = 1024;
constexpr int H   = 16;
constexpr int DH  = 64;
constexpr int BHn = Bb * H;       // 64
constexpr int M   = Bb * T;       // 8192
constexpr int KD  = Dm;           // 1024
constexpr int NQKV = 3 * Dm;      // 3072

__device__ __align__(256) __nv_bfloat16 g_xh[(size_t)M * KD],     g_xl[(size_t)M * KD];
__device__ __align__(256) __nv_bfloat16 g_w1h[(size_t)KD * NQKV], g_w1l[(size_t)KD * NQKV];
__device__ __align__(256) __nv_bfloat16 g_w2h[(size_t)KD * Dm],   g_w2l[(size_t)KD * Dm];
__device__ __align__(256) float         g_Qf[(size_t)BHn * T * DH], g_Kf[(size_t)BHn * T * DH];
__device__ __align__(256) __nv_bfloat16 g_Qh[(size_t)BHn * T * DH], g_Ql[(size_t)BHn * T * DH];
__device__ __align__(256) __nv_bfloat16 g_Kh[(size_t)BHn * T * DH], g_Kl[(size_t)BHn * T * DH];
__device__ __align__(256) __nv_bfloat16 g_Vh[(size_t)BHn * T * DH], g_Vl[(size_t)BHn * T * DH];
__device__ __align__(256) __nv_bfloat16 g_AOh[(size_t)M * Dm],      g_AOl[(size_t)M * Dm];

__device__ __forceinline__ void cp16(unsigned dst, const void* src) {
    asm volatile("cp.async.cg.shared.global [%0], [%1], 16;\n" :: "r"(dst), "l"(src));
}
#define CP_COMMIT()    asm volatile("cp.async.commit_group;\n" ::: "memory")
#define CP_WAIT_G1()   asm volatile("cp.async.wait_group 1;\n" ::: "memory")

__device__ __forceinline__ void ldsm4(unsigned* r, unsigned a) {
    asm volatile("ldmatrix.sync.aligned.m8n8.x4.shared.b16 {%0,%1,%2,%3}, [%4];\n"
                 : "=r"(r[0]), "=r"(r[1]), "=r"(r[2]), "=r"(r[3]) : "r"(a));
}
__device__ __forceinline__ void ldsm4t(unsigned* r, unsigned a) {
    asm volatile("ldmatrix.sync.aligned.m8n8.x4.trans.shared.b16 {%0,%1,%2,%3}, [%4];\n"
                 : "=r"(r[0]), "=r"(r[1]), "=r"(r[2]), "=r"(r[3]) : "r"(a));
}
__device__ __forceinline__ void mma16816(float* c, const unsigned* a, const unsigned* b) {
    asm volatile("mma.sync.aligned.m16n8k16.row.col.f32.bf16.bf16.f32 "
                 "{%0,%1,%2,%3}, {%4,%5,%6,%7}, {%8,%9}, {%0,%1,%2,%3};\n"
                 : "+f"(c[0]), "+f"(c[1]), "+f"(c[2]), "+f"(c[3])
                 : "r"(a[0]), "r"(a[1]), "r"(a[2]), "r"(a[3]), "r"(b[0]), "r"(b[1]));
}
__device__ __forceinline__ unsigned pack2f(float a, float b) {
    __nv_bfloat162 t = __floats2bfloat162_rn(a, b);
    return *reinterpret_cast<unsigned*>(&t);
}

// ---------------------------------------------------------------------------
// fp32 -> (hi, lo) bf16 split. DST: 0 = x, 1 = Wqkv, 2 = Wproj.
// ---------------------------------------------------------------------------
template <int DST>
__global__ void split4_kernel(const float4* __restrict__ src, int n4)
{
    __nv_bfloat162* dh = reinterpret_cast<__nv_bfloat162*>(
        DST == 0 ? g_xh : DST == 1 ? g_w1h : g_w2h);
    __nv_bfloat162* dl = reinterpret_cast<__nv_bfloat162*>(
        DST == 0 ? g_xl : DST == 1 ? g_w1l : g_w2l);
    int i = blockIdx.x * blockDim.x + threadIdx.x;
    if (i >= n4) return;
    float4 v = src[i];
    __nv_bfloat16 h0 = __float2bfloat16_rn(v.x), h1 = __float2bfloat16_rn(v.y);
    __nv_bfloat16 h2 = __float2bfloat16_rn(v.z), h3 = __float2bfloat16_rn(v.w);
    dh[2 * i]     = __halves2bfloat162(h0, h1);
    dh[2 * i + 1] = __halves2bfloat162(h2, h3);
    dl[2 * i]     = __floats2bfloat162_rn(v.x - __bfloat162float(h0), v.y - __bfloat162float(h1));
    dl[2 * i + 1] = __floats2bfloat162_rn(v.z - __bfloat162float(h2), v.w - __bfloat162float(h3));
}

// ---------------------------------------------------------------------------
// GEMM (R9, unchanged): 128x128x32, 256 thr, 3-stage cp.async, 2 CTAs/SM.
// ---------------------------------------------------------------------------
constexpr int APITCH = 40;
constexpr int BPITCH = 136;
constexpr int A_ELE  = 128 * APITCH;
constexpr int B_ELE  = 32 * BPITCH;
constexpr int GSTAGE = 2 * A_ELE + 2 * B_ELE;
constexpr int GSMEM  = 3 * GSTAGE * 2;

template <int MODE>
__global__ __launch_bounds__(256, 2)
void gemm_bf16(const float* __restrict__ bias, float* __restrict__ Cout, int N)
{
    const __nv_bfloat16* __restrict__ Ah = (MODE == 0) ? g_xh  : g_AOh;
    const __nv_bfloat16* __restrict__ Al = (MODE == 0) ? g_xl  : g_AOl;
    const __nv_bfloat16* __restrict__ Bh = (MODE == 0) ? g_w1h : g_w2h;
    const __nv_bfloat16* __restrict__ Bl = (MODE == 0) ? g_w1l : g_w2l;

    extern __shared__ __nv_bfloat16 gsm[];
    const int tid = threadIdx.x;
    const int m0 = blockIdx.y * 128, n0 = blockIdx.x * 128;
    const int wid = tid >> 5, lane = tid & 31;
    const int wm = wid >> 2, wn = wid & 3;
    const int g = lane >> 2, q = lane & 3;
    const int seg = lane >> 3, l7 = lane & 7;
    const unsigned sbase = (unsigned)__cvta_generic_to_shared(gsm);

    auto loadStage = [&](int stage, int k0) {
        unsigned sb = sbase + stage * GSTAGE * 2;
#pragma unroll
        for (int i = 0; i < 4; i++) {
            int cid = tid + 256 * i, prec = cid >> 9;
            int r = (cid & 511) >> 2, c = cid & 3;
            const __nv_bfloat16* src = (prec ? Al : Ah) + (size_t)(m0 + r) * KD + k0 + c * 8;
            cp16(sb + (prec * A_ELE + r * APITCH + c * 8) * 2, src);
        }
#pragma unroll
        for (int i = 0; i < 4; i++) {
            int cid = tid + 256 * i, prec = cid >> 9;
            int rr = (cid & 511) >> 4, cc = cid & 15;
            const __nv_bfloat16* src = (prec ? Bl : Bh) + (size_t)(k0 + rr) * N + n0 + cc * 8;
            cp16(sb + (2 * A_ELE + prec * B_ELE + rr * BPITCH + cc * 8) * 2, src);
        }
    };

    float acc[4][4][4];
#pragma unroll
    for (int a = 0; a < 4; a++)
#pragma unroll
        for (int b = 0; b < 4; b++)
#pragma unroll
            for (int c = 0; c < 4; c++) acc[a][b][c] = 0.f;

    constexpr int NIT = KD / 32;
    loadStage(0, 0);  CP_COMMIT();
    loadStage(1, 32); CP_COMMIT();
    for (int it = 0; it < NIT; ++it) {
        CP_WAIT_G1();
        __syncthreads();
        if (it + 2 < NIT) loadStage((it + 2) % 3, (it + 2) * 32);
        CP_COMMIT();
        unsigned sb = sbase + (it % 3) * GSTAGE * 2;
        unsigned bB = sb + 2 * A_ELE * 2;
#pragma unroll
        for (int ks = 0; ks < 2; ks++) {
            const int kb = ks * 16;
            unsigned bhf[2][4], blf[2][4];
#pragma unroll
            for (int np = 0; np < 2; np++) {
                int rr = kb + l7 + (seg & 1) * 8;
                int cc = wn * 32 + np * 16 + ((seg >> 1) & 1) * 8;
                unsigned bd = bB + (rr * BPITCH + cc) * 2;
                ldsm4t(bhf[np], bd);
                ldsm4t(blf[np], bd + B_ELE * 2);
            }
#pragma unroll
            for (int mt = 0; mt < 4; mt++) {
                int r2 = wm * 64 + mt * 16 + l7 + (seg & 1) * 8;
                int c2 = kb + ((seg >> 1) & 1) * 8;
                unsigned ad = sb + (r2 * APITCH + c2) * 2;
                unsigned ah[4], al[4];
                ldsm4(ah, ad);
                ldsm4(al, ad + A_ELE * 2);
#pragma unroll
                for (int nt = 0; nt < 4; nt++)
                    mma16816(acc[mt][nt], ah, &bhf[nt >> 1][(nt & 1) * 2]);
#pragma unroll
                for (int nt = 0; nt < 4; nt++)
                    mma16816(acc[mt][nt], ah, &blf[nt >> 1][(nt & 1) * 2]);
#pragma unroll
                for (int nt = 0; nt < 4; nt++)
                    mma16816(acc[mt][nt], al, &bhf[nt >> 1][(nt & 1) * 2]);
            }
        }
    }

#pragma unroll
    for (int mt = 0; mt < 4; mt++)
#pragma unroll
        for (int i = 0; i < 2; i++) {
            const int row = m0 + wm * 64 + mt * 16 + g + i * 8;
#pragma unroll
            for (int nt = 0; nt < 4; nt++)
#pragma unroll
                for (int j = 0; j < 2; j++) {
                    const int col = n0 + wn * 32 + nt * 8 + 2 * q + j;
                    const float v = acc[mt][nt][i * 2 + j] + bias[col];
                    if (MODE == 1) {
                        Cout[(size_t)row * N + col] = v;
                    } else {
                        const int sel = col >> 10;
                        const int rem = col & 1023;
                        const int hh = rem >> 6, dd = rem & 63;
                        const int b = row >> 11, t = row & 2047;
                        const size_t o = (((size_t)(b * H + hh)) * T + t) * DH + dd;
                        if (sel == 0)      g_Qf[o] = v;
                        else if (sel == 1) g_Kf[o] = v;
                        else {
                            __nv_bfloat16 h = __float2bfloat16_rn(v);
                            g_Vh[o] = h;
                            g_Vl[o] = __float2bfloat16_rn(v - __bfloat162float(h));
                        }
                    }
                }
        }
}

// ---------------------------------------------------------------------------
// RoPE (unchanged)
// ---------------------------------------------------------------------------
__global__ void rope_split_kernel(const float* __restrict__ cosT,
                                  const float* __restrict__ sinT)
{
    const int idx = blockIdx.x * blockDim.x + threadIdx.x;
    const int d   = idx & 31;
    const int t   = (idx >> 5) & (T - 1);
    const int bh  = (idx >> 16) & (BHn - 1);
    const int arr = idx >> 22;
    const float* P = arr ? g_Kf : g_Qf;
    __nv_bfloat16* Ph = arr ? g_Kh : g_Qh;
    __nv_bfloat16* Pl = arr ? g_Kl : g_Ql;
    const size_t base = ((size_t)bh * T + t) * DH;
    const float u1 = P[base + d], u2 = P[base + d + 32];
    const float c = cosT[t * DH + d], s = sinT[t * DH + d];
    float o1 = u1 * c - u2 * s;
    float o2 = u2 * c + u1 * s;
    if (arr == 0) { o1 *= 0.125f; o2 *= 0.125f; }
    __nv_bfloat16 h1 = __float2bfloat16_rn(o1), h2 = __float2bfloat16_rn(o2);
    Ph[base + d]      = h1;
    Pl[base + d]      = __float2bfloat16_rn(o1 - __bfloat162float(h1));
    Ph[base + d + 32] = h2;
    Pl[base + d + 32] = __float2bfloat16_rn(o2 - __bfloat162float(h2));
}

// ---------------------------------------------------------------------------
// Flash attention: 128 thr (4 warps), 64 q-rows/CTA, 2-stage K/V pipeline,
// 3 CTAs/SM. Prefetch issued AFTER the barrier (race-safe double buffer).
// ---------------------------------------------------------------------------
constexpr int FPITCH = 72;
constexpr int FTILE  = 64 * FPITCH;
constexpr int FSTAGE = 4 * FTILE;             // Kh,Kl,Vh,Vl
constexpr int FSMEM  = 2 * FSTAGE * 2;        // 73728 bytes

__global__ __launch_bounds__(128, 3)
void flash_bf16()
{
    extern __shared__ __nv_bfloat16 fsm[];
    const int tid = threadIdx.x, lane = tid & 31, w = tid >> 5;
    const int g = lane >> 2, q = lane & 3;
    const int seg = lane >> 3, l7 = lane & 7;
    const int bh = blockIdx.y, q0 = blockIdx.x * 64;
    const size_t hb = (size_t)bh * T * DH;
    const unsigned sbase = (unsigned)__cvta_generic_to_shared(fsm);

    unsigned qh[4][4], ql[4][4];
    {
        const unsigned* Qh32 = (const unsigned*)(g_Qh + hb);
        const unsigned* Ql32 = (const unsigned*)(g_Ql + hb);
        const int r0 = q0 + w * 16 + g;
#pragma unroll
        for (int ks = 0; ks < 4; ks++) {
            const int c = ks * 8 + q;
            qh[ks][0] = Qh32[r0 * 32 + c];
            qh[ks][1] = Qh32[(r0 + 8) * 32 + c];
            qh[ks][2] = Qh32[r0 * 32 + c + 4];
            qh[ks][3] = Qh32[(r0 + 8) * 32 + c + 4];
            ql[ks][0] = Ql32[r0 * 32 + c];
            ql[ks][1] = Ql32[(r0 + 8) * 32 + c];
            ql[ks][2] = Ql32[r0 * 32 + c + 4];
            ql[ks][3] = Ql32[(r0 + 8) * 32 + c + 4];
        }
    }

    float oacc[8][4];
#pragma unroll
    for (int a = 0; a < 8; a++)
#pragma unroll
        for (int b = 0; b < 4; b++) oacc[a][b] = 0.f;
    float m_i[2] = {-1e30f, -1e30f}, l_i[2] = {0.f, 0.f};

    auto loadKV = [&](int stage, int n0) {
        unsigned sb = sbase + stage * FSTAGE * 2;
        const __nv_bfloat16* srcs[4] = {
            g_Kh + hb + (size_t)n0 * DH, g_Kl + hb + (size_t)n0 * DH,
            g_Vh + hb + (size_t)n0 * DH, g_Vl + hb + (size_t)n0 * DH };
#pragma unroll
        for (int a = 0; a < 4; a++)
#pragma unroll
            for (int i = 0; i < 4; i++) {
                int cid = tid + 128 * i;              // 0..511
                int r = cid >> 3, c = cid & 7;
                cp16(sb + (a * FTILE + r * FPITCH + c * 8) * 2, srcs[a] + r * 64 + c * 8);
            }
    };

    constexpr int NIT = T / 64;        // 32
    loadKV(0, 0);
    CP_COMMIT();

    for (int it = 0; it < NIT; ++it) {
        __syncthreads();               // all warps done reading stage (it+1)&1
        if (it + 1 < NIT) loadKV((it + 1) & 1, (it + 1) * 64);
        CP_COMMIT();
        CP_WAIT_G1();                  // stage it&1 landed

        unsigned sb = sbase + (it & 1) * FSTAGE * 2;
        unsigned kh = sb, kl = sb + FTILE * 2;
        unsigned vh = sb + 2 * FTILE * 2, vl = sb + 3 * FTILE * 2;

        // ---- S = Q @ K^T ----
        float sacc[8][4];
#pragma unroll
        for (int a = 0; a < 8; a++)
#pragma unroll
            for (int b = 0; b < 4; b++) sacc[a][b] = 0.f;
#pragma unroll
        for (int ks = 0; ks < 4; ks++) {
            const int kb = ks * 16;
#pragma unroll
            for (int npp = 0; npp < 2; npp++) {
                unsigned bkh[2][4], bkl[2][4];
#pragma unroll
                for (int j = 0; j < 2; j++) {
                    const int np = 2 * npp + j;
                    const int nr = np * 16 + l7 + ((seg >> 1) & 1) * 8;
                    const int kc = kb + (seg & 1) * 8;
                    const unsigned off = (nr * FPITCH + kc) * 2;
                    ldsm4(bkh[j], kh + off);
                    ldsm4(bkl[j], kl + off);
                }
                float *a0 = sacc[4 * npp], *a1 = sacc[4 * npp + 1];
                float *a2 = sacc[4 * npp + 2], *a3 = sacc[4 * npp + 3];
                mma16816(a0, qh[ks], bkh[0]); mma16816(a1, qh[ks], bkh[0] + 2);
                mma16816(a2, qh[ks], bkh[1]); mma16816(a3, qh[ks], bkh[1] + 2);
                mma16816(a0, qh[ks], bkl[0]); mma16816(a1, qh[ks], bkl[0] + 2);
                mma16816(a2, qh[ks], bkl[1]); mma16816(a3, qh[ks], bkl[1] + 2);
                mma16816(a0, ql[ks], bkh[0]); mma16816(a1, ql[ks], bkh[0] + 2);
                mma16816(a2, ql[ks], bkh[1]); mma16816(a3, ql[ks], bkh[1] + 2);
            }
        }

        // ---- online softmax ----
#pragma unroll
        for (int r = 0; r < 2; r++) {
            float mx = -1e30f;
#pragma unroll
            for (int nt = 0; nt < 8; nt++)
                mx = fmaxf(mx, fmaxf(sacc[nt][2 * r], sacc[nt][2 * r + 1]));
            mx = fmaxf(mx, __shfl_xor_sync(0xffffffffu, mx, 1));
            mx = fmaxf(mx, __shfl_xor_sync(0xffffffffu, mx, 2));
            const float mnew = fmaxf(m_i[r], mx);
            const float corr = __expf(m_i[r] - mnew);
            m_i[r] = mnew;
            float rs = 0.f;
#pragma unroll
            for (int nt = 0; nt < 8; nt++) {
                sacc[nt][2 * r]     = __expf(sacc[nt][2 * r] - mnew);
                sacc[nt][2 * r + 1] = __expf(sacc[nt][2 * r + 1] - mnew);
                rs += sacc[nt][2 * r] + sacc[nt][2 * r + 1];
            }
            rs += __shfl_xor_sync(0xffffffffu, rs, 1);
            rs += __shfl_xor_sync(0xffffffffu, rs, 2);
            l_i[r] = l_i[r] * corr + rs;
#pragma unroll
            for (int nt = 0; nt < 8; nt++) {
                oacc[nt][2 * r]     *= corr;
                oacc[nt][2 * r + 1] *= corr;
            }
        }

        // ---- pack P hi/lo (S C-frag layout == PV A-frag layout) ----
        unsigned ph[16], pl[16];
#pragma unroll
        for (int nt = 0; nt < 8; nt++)
#pragma unroll
            for (int hf = 0; hf < 2; hf++) {
                const float p0 = sacc[nt][2 * hf], p1 = sacc[nt][2 * hf + 1];
                const __nv_bfloat16 b0 = __float2bfloat16_rn(p0);
                const __nv_bfloat16 b1 = __float2bfloat16_rn(p1);
                __nv_bfloat162 hi2 = __halves2bfloat162(b0, b1);
                ph[nt * 2 + hf] = *reinterpret_cast<unsigned*>(&hi2);
                pl[nt * 2 + hf] = pack2f(p0 - __bfloat162float(b0), p1 - __bfloat162float(b1));
            }

        // ---- O += P @ V ----
#pragma unroll
        for (int ks = 0; ks < 4; ks++) {
            const unsigned* aP  = &ph[4 * ks];
            const unsigned* aPl = &pl[4 * ks];
#pragma unroll
            for (int npp = 0; npp < 2; npp++) {
                unsigned bvh[2][4], bvl[2][4];
#pragma unroll
                for (int j = 0; j < 2; j++) {
                    const int np = 2 * npp + j;
                    const int vr = ks * 16 + l7 + (seg & 1) * 8;
                    const int vc = np * 16 + ((seg >> 1) & 1) * 8;
                    const unsigned off = (vr * FPITCH + vc) * 2;
                    ldsm4t(bvh[j], vh + off);
                    ldsm4t(bvl[j], vl + off);
                }
                float *a0 = oacc[4 * npp], *a1 = oacc[4 * npp + 1];
                float *a2 = oacc[4 * npp + 2], *a3 = oacc[4 * npp + 3];
                mma16816(a0, aP, bvh[0]);  mma16816(a1, aP, bvh[0] + 2);
                mma16816(a2, aP, bvh[1]);  mma16816(a3, aP, bvh[1] + 2);
                mma16816(a0, aP, bvl[0]);  mma16816(a1, aP, bvl[0] + 2);
                mma16816(a2, aP, bvl[1]);  mma16816(a3, aP, bvl[1] + 2);
                mma16816(a0, aPl, bvh[0]); mma16816(a1, aPl, bvh[0] + 2);
                mma16816(a2, aPl, bvh[1]); mma16816(a3, aPl, bvh[1] + 2);
            }
        }
    }

    // ---- epilogue: normalize, split, store pre-split AO ----
    const int b = bh >> 4, h = bh & 15;
#pragma unroll
    for (int r = 0; r < 2; r++) {
        const float inv = 1.f / l_i[r];
        const int t = q0 + w * 16 + g + r * 8;
        const size_t base = ((size_t)(b * T + t)) * Dm + h * DH;
#pragma unroll
        for (int nt = 0; nt < 8; nt++) {
            const float v0 = oacc[nt][2 * r] * inv;
            const float v1 = oacc[nt][2 * r + 1] * inv;
            const __nv_bfloat16 h0 = __float2bfloat16_rn(v0);
            const __nv_bfloat16 h1 = __float2bfloat16_rn(v1);
            *reinterpret_cast<__nv_bfloat162*>(g_AOh + base + nt * 8 + 2 * q) =
                __halves2bfloat162(h0, h1);
            *reinterpret_cast<__nv_bfloat162*>(g_AOl + base + nt * 8 + 2 * q) =
                __floats2bfloat162_rn(v0 - __bfloat162float(h0), v1 - __bfloat162float(h1));
        }
    }
}

// ---------------------------------------------------------------------------
extern "C" void kernel_launch(void* const* d_in, const int* in_sizes, int n_in,
                              void* d_out, int out_size)
{
    (void)in_sizes; (void)n_in; (void)out_size;
    const float* x     = (const float*)d_in[0];
    const float* Wqkv  = (const float*)d_in[1];
    const float* bqkv  = (const float*)d_in[2];
    const float* Wproj = (const float*)d_in[3];
    const float* bproj = (const float*)d_in[4];
    const float* cosT  = (const float*)d_in[5];
    const float* sinT  = (const float*)d_in[6];
    float* out = (float*)d_out;

    cudaFuncSetAttribute(gemm_bf16<0>, cudaFuncAttributeMaxDynamicSharedMemorySize, GSMEM);
    cudaFuncSetAttribute(gemm_bf16<1>, cudaFuncAttributeMaxDynamicSharedMemorySize, GSMEM);
    cudaFuncSetAttribute(flash_bf16,   cudaFuncAttributeMaxDynamicSharedMemorySize, FSMEM);

    split4_kernel<0><<<(M * KD / 4 + 255) / 256, 256>>>((const float4*)x, M * KD / 4);
    split4_kernel<1><<<(KD * NQKV / 4 + 255) / 256, 256>>>((const float4*)Wqkv, KD * NQKV / 4);
    split4_kernel<2><<<(KD * Dm / 4 + 255) / 256, 256>>>((const float4*)Wproj, KD * Dm / 4);

    gemm_bf16<0><<<dim3(NQKV / 128, M / 128), 256, GSMEM>>>(bqkv, nullptr, NQKV);

    rope_split_kernel<<<(2 * BHn * T * 32) / 256, 256>>>(cosT, sinT);

    flash_bf16<<<dim3(T / 64, BHn), 128, FSMEM>>>();

    gemm_bf16<1><<<dim3(Dm / 128, M / 128), 256, GSMEM>>>(bproj, out, Dm);
}

// round 16
// speedup vs baseline: 2.3032x; 1.1716x over previous
#include <cuda_runtime.h>
#include <cuda_bf16.h>
#include <cuda_fp16.h>

// ---------------------------------------------------------------------------
// FlashMultiHeadAttention. R16: dense GEMMs switched to 2-term fp16 HMMA
// (A single fp16, B two-limb fp16 -> 2 MMAs per k16 instead of 3).
// Flash attention unchanged (3-term split-bf16, proven 2.26e-5 core).
// ---------------------------------------------------------------------------

constexpr int Bb  = 4;
constexpr int T   = 2048;
constexpr int Dm  = 1024;
constexpr int H   = 16;
constexpr int DH  = 64;
constexpr int BHn = Bb * H;       // 64
constexpr int M   = Bb * T;       // 8192
constexpr int KD  = Dm;           // 1024
constexpr int NQKV = 3 * Dm;      // 3072

// ---- scratch ---------------------------------------------------------------
__device__ __align__(256) __half g_xa[(size_t)M * KD];                       // A of gemm0 (single fp16)
__device__ __align__(256) __half g_w1h[(size_t)KD * NQKV], g_w1l[(size_t)KD * NQKV]; // [k][n]
__device__ __align__(256) __half g_w2h[(size_t)KD * Dm],   g_w2l[(size_t)KD * Dm];   // [k][n]
__device__ __align__(256) __half g_AOa[(size_t)M * Dm];                      // A of gemm1 (single fp16)
__device__ __align__(256) float g_Qf[(size_t)BHn * T * DH], g_Kf[(size_t)BHn * T * DH];
__device__ __align__(256) __nv_bfloat16 g_Qh[(size_t)BHn * T * DH], g_Ql[(size_t)BHn * T * DH];
__device__ __align__(256) __nv_bfloat16 g_Kh[(size_t)BHn * T * DH], g_Kl[(size_t)BHn * T * DH];
__device__ __align__(256) __nv_bfloat16 g_Vh[(size_t)BHn * T * DH], g_Vl[(size_t)BHn * T * DH];

// ---- PTX helpers -----------------------------------------------------------
__device__ __forceinline__ void cp16(unsigned dst, const void* src) {
    asm volatile("cp.async.cg.shared.global [%0], [%1], 16;\n" :: "r"(dst), "l"(src));
}
#define CP_COMMIT()    asm volatile("cp.async.commit_group;\n" ::: "memory")
#define CP_WAIT_G1()   asm volatile("cp.async.wait_group 1;\n" ::: "memory")

__device__ __forceinline__ void ldsm4(unsigned* r, unsigned a) {
    asm volatile("ldmatrix.sync.aligned.m8n8.x4.shared.b16 {%0,%1,%2,%3}, [%4];\n"
                 : "=r"(r[0]), "=r"(r[1]), "=r"(r[2]), "=r"(r[3]) : "r"(a));
}
__device__ __forceinline__ void ldsm4t(unsigned* r, unsigned a) {
    asm volatile("ldmatrix.sync.aligned.m8n8.x4.trans.shared.b16 {%0,%1,%2,%3}, [%4];\n"
                 : "=r"(r[0]), "=r"(r[1]), "=r"(r[2]), "=r"(r[3]) : "r"(a));
}
__device__ __forceinline__ void mma16816(float* c, const unsigned* a, const unsigned* b) {
    asm volatile("mma.sync.aligned.m16n8k16.row.col.f32.bf16.bf16.f32 "
                 "{%0,%1,%2,%3}, {%4,%5,%6,%7}, {%8,%9}, {%0,%1,%2,%3};\n"
                 : "+f"(c[0]), "+f"(c[1]), "+f"(c[2]), "+f"(c[3])
                 : "r"(a[0]), "r"(a[1]), "r"(a[2]), "r"(a[3]), "r"(b[0]), "r"(b[1]));
}
__device__ __forceinline__ void mma_h(float* c, const unsigned* a, const unsigned* b) {
    asm volatile("mma.sync.aligned.m16n8k16.row.col.f32.f16.f16.f32 "
                 "{%0,%1,%2,%3}, {%4,%5,%6,%7}, {%8,%9}, {%0,%1,%2,%3};\n"
                 : "+f"(c[0]), "+f"(c[1]), "+f"(c[2]), "+f"(c[3])
                 : "r"(a[0]), "r"(a[1]), "r"(a[2]), "r"(a[3]), "r"(b[0]), "r"(b[1]));
}
__device__ __forceinline__ unsigned pack2f(float a, float b) {
    __nv_bfloat162 t = __floats2bfloat162_rn(a, b);
    return *reinterpret_cast<unsigned*>(&t);
}

// ---------------------------------------------------------------------------
// Quant kernels.
// quantA: fp32 -> single fp16 (x).
// splitW: fp32 [k][n] -> fp16 hi/lo, same layout. DST: 1=Wqkv, 2=Wproj.
// ---------------------------------------------------------------------------
__global__ void quantA_kernel(const float4* __restrict__ src, int n4)
{
    __half2* d = reinterpret_cast<__half2*>(g_xa);
    int i = blockIdx.x * blockDim.x + threadIdx.x;
    if (i >= n4) return;
    float4 v = src[i];
    d[2 * i]     = __floats2half2_rn(v.x, v.y);
    d[2 * i + 1] = __floats2half2_rn(v.z, v.w);
}

template <int DST>
__global__ void splitW_kernel(const float4* __restrict__ src, int n4)
{
    __half2* dh = reinterpret_cast<__half2*>(DST == 1 ? g_w1h : g_w2h);
    __half2* dl = reinterpret_cast<__half2*>(DST == 1 ? g_w1l : g_w2l);
    int i = blockIdx.x * blockDim.x + threadIdx.x;
    if (i >= n4) return;
    float4 v = src[i];
    __half h0 = __float2half_rn(v.x), h1 = __float2half_rn(v.y);
    __half h2 = __float2half_rn(v.z), h3 = __float2half_rn(v.w);
    dh[2 * i]     = __halves2half2(h0, h1);
    dh[2 * i + 1] = __halves2half2(h2, h3);
    dl[2 * i]     = __floats2half2_rn(v.x - __half2float(h0), v.y - __half2float(h1));
    dl[2 * i + 1] = __floats2half2_rn(v.z - __half2float(h2), v.w - __half2float(h3));
}

// ---------------------------------------------------------------------------
// GEMM: C[M,N] = A[M,1024] @ B[1024,N] + bias, 2-term fp16 HMMA.
// A single fp16 (one smem array), B fp16 hi/lo. 128x128x32 tiles, 256 thr
// (8 warps 2x4), warp tile 64x32, 3-stage cp.async, 2 CTAs/SM.
// MODE 0: scatter Q/K fp32 + V bf16-split.  MODE 1: fp32 row-major out.
// ---------------------------------------------------------------------------
constexpr int APITCH = 40;                          // halves/row
constexpr int BPITCH = 136;                         // halves/row
constexpr int A_ELE  = 128 * APITCH;                // 5120 halves
constexpr int B_ELE  = 32 * BPITCH;                 // 4352 halves
constexpr int GSTAGE = A_ELE + 2 * B_ELE;           // 13824 halves / stage
constexpr int GSMEM  = 3 * GSTAGE * 2;              // 82944 bytes

template <int MODE>
__global__ __launch_bounds__(256, 2)
void gemm_h2(const float* __restrict__ bias, float* __restrict__ Cout, int N)
{
    const __half* __restrict__ Aa = (MODE == 0) ? g_xa  : g_AOa;
    const __half* __restrict__ Bh = (MODE == 0) ? g_w1h : g_w2h;
    const __half* __restrict__ Bl = (MODE == 0) ? g_w1l : g_w2l;

    extern __shared__ __half gsm[];
    const int tid = threadIdx.x;
    const int m0 = blockIdx.y * 128, n0 = blockIdx.x * 128;
    const int wid = tid >> 5, lane = tid & 31;
    const int wm = wid >> 2, wn = wid & 3;
    const int g = lane >> 2, q = lane & 3;
    const int seg = lane >> 3, l7 = lane & 7;
    const unsigned sbase = (unsigned)__cvta_generic_to_shared(gsm);

    auto loadStage = [&](int stage, int k0) {
        unsigned sb = sbase + stage * GSTAGE * 2;
        // 1536 chunks of 16B: 512 A + 1024 B (hi, lo)
#pragma unroll
        for (int i = 0; i < 6; i++) {
            int cid = tid + 256 * i;
            if (cid < 512) {                        // A: 128 rows x 4 chunks
                int r = cid >> 2, c = cid & 3;
                cp16(sb + (r * APITCH + c * 8) * 2, Aa + (size_t)(m0 + r) * KD + k0 + c * 8);
            } else {                                // B: 2 arrays x 32 rows x 16 chunks
                int cid2 = cid - 512;
                int prec = cid2 >> 9, idx = cid2 & 511;
                int rr = idx >> 4, cc = idx & 15;
                const __half* src = (prec ? Bl : Bh) + (size_t)(k0 + rr) * N + n0 + cc * 8;
                cp16(sb + (A_ELE + prec * B_ELE + rr * BPITCH + cc * 8) * 2, src);
            }
        }
    };

    float acc[4][4][4];
#pragma unroll
    for (int a = 0; a < 4; a++)
#pragma unroll
        for (int b = 0; b < 4; b++)
#pragma unroll
            for (int c = 0; c < 4; c++) acc[a][b][c] = 0.f;

    constexpr int NIT = KD / 32;
    loadStage(0, 0);  CP_COMMIT();
    loadStage(1, 32); CP_COMMIT();
    for (int it = 0; it < NIT; ++it) {
        CP_WAIT_G1();
        __syncthreads();
        if (it + 2 < NIT) loadStage((it + 2) % 3, (it + 2) * 32);
        CP_COMMIT();
        unsigned sb = sbase + (it % 3) * GSTAGE * 2;
        unsigned bB = sb + A_ELE * 2;
#pragma unroll
        for (int ks = 0; ks < 2; ks++) {
            const int kb = ks * 16;
            unsigned bhf[2][4], blf[2][4];
#pragma unroll
            for (int np = 0; np < 2; np++) {        // B frag (trans)
                int rr = kb + l7 + (seg & 1) * 8;
                int cc = wn * 32 + np * 16 + ((seg >> 1) & 1) * 8;
                unsigned bd = bB + (rr * BPITCH + cc) * 2;
                ldsm4t(bhf[np], bd);
                ldsm4t(blf[np], bd + B_ELE * 2);
            }
#pragma unroll
            for (int mt = 0; mt < 4; mt++) {
                int r2 = wm * 64 + mt * 16 + l7 + (seg & 1) * 8;
                int c2 = kb + ((seg >> 1) & 1) * 8;
                unsigned ah[4];
                ldsm4(ah, sb + (r2 * APITCH + c2) * 2);
                // term-major: Ah*Bh sweep, then Ah*Bl sweep
#pragma unroll
                for (int nt = 0; nt < 4; nt++)
                    mma_h(acc[mt][nt], ah, &bhf[nt >> 1][(nt & 1) * 2]);
#pragma unroll
                for (int nt = 0; nt < 4; nt++)
                    mma_h(acc[mt][nt], ah, &blf[nt >> 1][(nt & 1) * 2]);
            }
        }
    }

#pragma unroll
    for (int mt = 0; mt < 4; mt++)
#pragma unroll
        for (int i = 0; i < 2; i++) {
            const int row = m0 + wm * 64 + mt * 16 + g + i * 8;
#pragma unroll
            for (int nt = 0; nt < 4; nt++)
#pragma unroll
                for (int j = 0; j < 2; j++) {
                    const int col = n0 + wn * 32 + nt * 8 + 2 * q + j;
                    const float v = acc[mt][nt][i * 2 + j] + bias[col];
                    if (MODE == 1) {
                        Cout[(size_t)row * N + col] = v;
                    } else {
                        const int sel = col >> 10;
                        const int rem = col & 1023;
                        const int hh = rem >> 6, dd = rem & 63;
                        const int b = row >> 11, t = row & 2047;
                        const size_t o = (((size_t)(b * H + hh)) * T + t) * DH + dd;
                        if (sel == 0)      g_Qf[o] = v;
                        else if (sel == 1) g_Kf[o] = v;
                        else {
                            __nv_bfloat16 h = __float2bfloat16_rn(v);
                            g_Vh[o] = h;
                            g_Vl[o] = __float2bfloat16_rn(v - __bfloat162float(h));
                        }
                    }
                }
        }
}

// ---------------------------------------------------------------------------
// RoPE (unchanged)
// ---------------------------------------------------------------------------
__global__ void rope_split_kernel(const float* __restrict__ cosT,
                                  const float* __restrict__ sinT)
{
    const int idx = blockIdx.x * blockDim.x + threadIdx.x;
    const int d   = idx & 31;
    const int t   = (idx >> 5) & (T - 1);
    const int bh  = (idx >> 16) & (BHn - 1);
    const int arr = idx >> 22;
    const float* P = arr ? g_Kf : g_Qf;
    __nv_bfloat16* Ph = arr ? g_Kh : g_Qh;
    __nv_bfloat16* Pl = arr ? g_Kl : g_Ql;
    const size_t base = ((size_t)bh * T + t) * DH;
    const float u1 = P[base + d], u2 = P[base + d + 32];
    const float c = cosT[t * DH + d], s = sinT[t * DH + d];
    float o1 = u1 * c - u2 * s;
    float o2 = u2 * c + u1 * s;
    if (arr == 0) { o1 *= 0.125f; o2 *= 0.125f; }
    __nv_bfloat16 h1 = __float2bfloat16_rn(o1), h2 = __float2bfloat16_rn(o2);
    Ph[base + d]      = h1;
    Pl[base + d]      = __float2bfloat16_rn(o1 - __bfloat162float(h1));
    Ph[base + d + 32] = h2;
    Pl[base + d + 32] = __float2bfloat16_rn(o2 - __bfloat162float(h2));
}

// ---------------------------------------------------------------------------
// Flash attention (R15 structure): 128 thr, 64 q-rows/CTA, 2-stage K/V,
// 3 CTAs/SM. Epilogue now writes single fp16 AO (A of gemm1).
// ---------------------------------------------------------------------------
constexpr int FPITCH = 72;
constexpr int FTILE  = 64 * FPITCH;
constexpr int FSTAGE = 4 * FTILE;
constexpr int FSMEM  = 2 * FSTAGE * 2;        // 73728 bytes

__global__ __launch_bounds__(128, 3)
void flash_bf16()
{
    extern __shared__ __nv_bfloat16 fsm[];
    const int tid = threadIdx.x, lane = tid & 31, w = tid >> 5;
    const int g = lane >> 2, q = lane & 3;
    const int seg = lane >> 3, l7 = lane & 7;
    const int bh = blockIdx.y, q0 = blockIdx.x * 64;
    const size_t hb = (size_t)bh * T * DH;
    const unsigned sbase = (unsigned)__cvta_generic_to_shared(fsm);

    unsigned qh[4][4], ql[4][4];
    {
        const unsigned* Qh32 = (const unsigned*)(g_Qh + hb);
        const unsigned* Ql32 = (const unsigned*)(g_Ql + hb);
        const int r0 = q0 + w * 16 + g;
#pragma unroll
        for (int ks = 0; ks < 4; ks++) {
            const int c = ks * 8 + q;
            qh[ks][0] = Qh32[r0 * 32 + c];
            qh[ks][1] = Qh32[(r0 + 8) * 32 + c];
            qh[ks][2] = Qh32[r0 * 32 + c + 4];
            qh[ks][3] = Qh32[(r0 + 8) * 32 + c + 4];
            ql[ks][0] = Ql32[r0 * 32 + c];
            ql[ks][1] = Ql32[(r0 + 8) * 32 + c];
            ql[ks][2] = Ql32[r0 * 32 + c + 4];
            ql[ks][3] = Ql32[(r0 + 8) * 32 + c + 4];
        }
    }

    float oacc[8][4];
#pragma unroll
    for (int a = 0; a < 8; a++)
#pragma unroll
        for (int b = 0; b < 4; b++) oacc[a][b] = 0.f;
    float m_i[2] = {-1e30f, -1e30f}, l_i[2] = {0.f, 0.f};

    auto loadKV = [&](int stage, int n0) {
        unsigned sb = sbase + stage * FSTAGE * 2;
        const __nv_bfloat16* srcs[4] = {
            g_Kh + hb + (size_t)n0 * DH, g_Kl + hb + (size_t)n0 * DH,
            g_Vh + hb + (size_t)n0 * DH, g_Vl + hb + (size_t)n0 * DH };
#pragma unroll
        for (int a = 0; a < 4; a++)
#pragma unroll
            for (int i = 0; i < 4; i++) {
                int cid = tid + 128 * i;
                int r = cid >> 3, c = cid & 7;
                cp16(sb + (a * FTILE + r * FPITCH + c * 8) * 2, srcs[a] + r * 64 + c * 8);
            }
    };

    constexpr int NIT = T / 64;
    loadKV(0, 0);
    CP_COMMIT();

    for (int it = 0; it < NIT; ++it) {
        __syncthreads();
        if (it + 1 < NIT) loadKV((it + 1) & 1, (it + 1) * 64);
        CP_COMMIT();
        CP_WAIT_G1();

        unsigned sb = sbase + (it & 1) * FSTAGE * 2;
        unsigned kh = sb, kl = sb + FTILE * 2;
        unsigned vh = sb + 2 * FTILE * 2, vl = sb + 3 * FTILE * 2;

        float sacc[8][4];
#pragma unroll
        for (int a = 0; a < 8; a++)
#pragma unroll
            for (int b = 0; b < 4; b++) sacc[a][b] = 0.f;
#pragma unroll
        for (int ks = 0; ks < 4; ks++) {
            const int kb = ks * 16;
#pragma unroll
            for (int npp = 0; npp < 2; npp++) {
                unsigned bkh[2][4], bkl[2][4];
#pragma unroll
                for (int j = 0; j < 2; j++) {
                    const int np = 2 * npp + j;
                    const int nr = np * 16 + l7 + ((seg >> 1) & 1) * 8;
                    const int kc = kb + (seg & 1) * 8;
                    const unsigned off = (nr * FPITCH + kc) * 2;
                    ldsm4(bkh[j], kh + off);
                    ldsm4(bkl[j], kl + off);
                }
                float *a0 = sacc[4 * npp], *a1 = sacc[4 * npp + 1];
                float *a2 = sacc[4 * npp + 2], *a3 = sacc[4 * npp + 3];
                mma16816(a0, qh[ks], bkh[0]); mma16816(a1, qh[ks], bkh[0] + 2);
                mma16816(a2, qh[ks], bkh[1]); mma16816(a3, qh[ks], bkh[1] + 2);
                mma16816(a0, qh[ks], bkl[0]); mma16816(a1, qh[ks], bkl[0] + 2);
                mma16816(a2, qh[ks], bkl[1]); mma16816(a3, qh[ks], bkl[1] + 2);
                mma16816(a0, ql[ks], bkh[0]); mma16816(a1, ql[ks], bkh[0] + 2);
                mma16816(a2, ql[ks], bkh[1]); mma16816(a3, ql[ks], bkh[1] + 2);
            }
        }

#pragma unroll
        for (int r = 0; r < 2; r++) {
            float mx = -1e30f;
#pragma unroll
            for (int nt = 0; nt < 8; nt++)
                mx = fmaxf(mx, fmaxf(sacc[nt][2 * r], sacc[nt][2 * r + 1]));
            mx = fmaxf(mx, __shfl_xor_sync(0xffffffffu, mx, 1));
            mx = fmaxf(mx, __shfl_xor_sync(0xffffffffu, mx, 2));
            const float mnew = fmaxf(m_i[r], mx);
            const float corr = __expf(m_i[r] - mnew);
            m_i[r] = mnew;
            float rs = 0.f;
#pragma unroll
            for (int nt = 0; nt < 8; nt++) {
                sacc[nt][2 * r]     = __expf(sacc[nt][2 * r] - mnew);
                sacc[nt][2 * r + 1] = __expf(sacc[nt][2 * r + 1] - mnew);
                rs += sacc[nt][2 * r] + sacc[nt][2 * r + 1];
            }
            rs += __shfl_xor_sync(0xffffffffu, rs, 1);
            rs += __shfl_xor_sync(0xffffffffu, rs, 2);
            l_i[r] = l_i[r] * corr + rs;
#pragma unroll
            for (int nt = 0; nt < 8; nt++) {
                oacc[nt][2 * r]     *= corr;
                oacc[nt][2 * r + 1] *= corr;
            }
        }

        unsigned ph[16], pl[16];
#pragma unroll
        for (int nt = 0; nt < 8; nt++)
#pragma unroll
            for (int hf = 0; hf < 2; hf++) {
                const float p0 = sacc[nt][2 * hf], p1 = sacc[nt][2 * hf + 1];
                const __nv_bfloat16 b0 = __float2bfloat16_rn(p0);
                const __nv_bfloat16 b1 = __float2bfloat16_rn(p1);
                __nv_bfloat162 hi2 = __halves2bfloat162(b0, b1);
                ph[nt * 2 + hf] = *reinterpret_cast<unsigned*>(&hi2);
                pl[nt * 2 + hf] = pack2f(p0 - __bfloat162float(b0), p1 - __bfloat162float(b1));
            }

#pragma unroll
        for (int ks = 0; ks < 4; ks++) {
            const unsigned* aP  = &ph[4 * ks];
            const unsigned* aPl = &pl[4 * ks];
#pragma unroll
            for (int npp = 0; npp < 2; npp++) {
                unsigned bvh[2][4], bvl[2][4];
#pragma unroll
                for (int j = 0; j < 2; j++) {
                    const int np = 2 * npp + j;
                    const int vr = ks * 16 + l7 + (seg & 1) * 8;
                    const int vc = np * 16 + ((seg >> 1) & 1) * 8;
                    const unsigned off = (vr * FPITCH + vc) * 2;
                    ldsm4t(bvh[j], vh + off);
                    ldsm4t(bvl[j], vl + off);
                }
                float *a0 = oacc[4 * npp], *a1 = oacc[4 * npp + 1];
                float *a2 = oacc[4 * npp + 2], *a3 = oacc[4 * npp + 3];
                mma16816(a0, aP, bvh[0]);  mma16816(a1, aP, bvh[0] + 2);
                mma16816(a2, aP, bvh[1]);  mma16816(a3, aP, bvh[1] + 2);
                mma16816(a0, aP, bvl[0]);  mma16816(a1, aP, bvl[0] + 2);
                mma16816(a2, aP, bvl[1]);  mma16816(a3, aP, bvl[1] + 2);
                mma16816(a0, aPl, bvh[0]); mma16816(a1, aPl, bvh[0] + 2);
                mma16816(a2, aPl, bvh[1]); mma16816(a3, aPl, bvh[1] + 2);
            }
        }
    }

    // epilogue: normalize, store AO as single fp16 (A operand of gemm1)
    const int b = bh >> 4, h = bh & 15;
#pragma unroll
    for (int r = 0; r < 2; r++) {
        const float inv = 1.f / l_i[r];
        const int t = q0 + w * 16 + g + r * 8;
        const size_t base = ((size_t)(b * T + t)) * Dm + h * DH;
#pragma unroll
        for (int nt = 0; nt < 8; nt++) {
            const float v0 = oacc[nt][2 * r] * inv;
            const float v1 = oacc[nt][2 * r + 1] * inv;
            *reinterpret_cast<__half2*>(g_AOa + base + nt * 8 + 2 * q) =
                __floats2half2_rn(v0, v1);
        }
    }
}

// ---------------------------------------------------------------------------
extern "C" void kernel_launch(void* const* d_in, const int* in_sizes, int n_in,
                              void* d_out, int out_size)
{
    (void)in_sizes; (void)n_in; (void)out_size;
    const float* x     = (const float*)d_in[0];
    const float* Wqkv  = (const float*)d_in[1];
    const float* bqkv  = (const float*)d_in[2];
    const float* Wproj = (const float*)d_in[3];
    const float* bproj = (const float*)d_in[4];
    const float* cosT  = (const float*)d_in[5];
    const float* sinT  = (const float*)d_in[6];
    float* out = (float*)d_out;

    cudaFuncSetAttribute(gemm_h2<0>, cudaFuncAttributeMaxDynamicSharedMemorySize, GSMEM);
    cudaFuncSetAttribute(gemm_h2<1>, cudaFuncAttributeMaxDynamicSharedMemorySize, GSMEM);
    cudaFuncSetAttribute(flash_bf16, cudaFuncAttributeMaxDynamicSharedMemorySize, FSMEM);

    quantA_kernel<<<(M * KD / 4 + 255) / 256, 256>>>((const float4*)x, M * KD / 4);
    splitW_kernel<1><<<(KD * NQKV / 4 + 255) / 256, 256>>>((const float4*)Wqkv, KD * NQKV / 4);
    splitW_kernel<2><<<(KD * Dm / 4 + 255) / 256, 256>>>((const float4*)Wproj, KD * Dm / 4);

    gemm_h2<0><<<dim3(NQKV / 128, M / 128), 256, GSMEM>>>(bqkv, nullptr, NQKV);

    rope_split_kernel<<<(2 * BHn * T * 32) / 256, 256>>>(cosT, sinT);

    flash_bf16<<<dim3(T / 64, BHn), 128, FSMEM>>>();

    gemm_h2<1><<<dim3(Dm / 128, M / 128), 256, GSMEM>>>(bproj, out, Dm);
}